// round 11
// baseline (speedup 1.0000x reference)
#include <cuda_runtime.h>
#include <cuda_bf16.h>
#include <math.h>
#include <stdint.h>

// Problem constants
#define LAYERS 2
#define NH     12
#define D      768
#define HS     64
#define FF     3072
#define VOCAB  50257
#define BATCH  4
#define TSEQ   512
#define ROWS   (BATCH * TSEQ)       // 2048
#define QKVN   (3 * D)              // 2304

// ---------------- scratch (static device globals; no allocation) --------------
__device__ float g_x[ROWS * D];
__device__ float g_qkv[ROWS * QKVN];
__device__ float g_rowsum[ROWS];
__device__ float g_bc2[LAYERS * QKVN];

// bf16 split operands
__device__ __nv_bfloat16 g_ah[ROWS * D];
__device__ __nv_bfloat16 g_al[ROWS * D];
__device__ __nv_bfloat16 g_ah2[ROWS * FF];
__device__ __nv_bfloat16 g_al2[ROWS * FF];
__device__ __nv_bfloat16 g_wteh[VOCAB * D];
__device__ __nv_bfloat16 g_wtel[VOCAB * D];
__device__ __nv_bfloat16 g_qkvwh[LAYERS * QKVN * D];
__device__ __nv_bfloat16 g_qkvwl[LAYERS * QKVN * D];
__device__ __nv_bfloat16 g_woh[LAYERS * D * D];
__device__ __nv_bfloat16 g_wol[LAYERS * D * D];
__device__ __nv_bfloat16 g_w1h[LAYERS * FF * D];
__device__ __nv_bfloat16 g_w1l[LAYERS * FF * D];
__device__ __nv_bfloat16 g_w2h[LAYERS * D * FF];
__device__ __nv_bfloat16 g_w2l[LAYERS * D * FF];

// ---------------- small helpers ----------------------------------------------
__device__ __forceinline__ float warp_sum(float v) {
    #pragma unroll
    for (int o = 16; o > 0; o >>= 1) v += __shfl_xor_sync(0xffffffffu, v, o);
    return v;
}

__device__ __forceinline__ uint32_t smem_u32(const void* p) {
    uint32_t a;
    asm("{ .reg .u64 t; cvta.to.shared.u64 t, %1; cvt.u32.u64 %0, t; }" : "=r"(a) : "l"(p));
    return a;
}

// fast exp on the FMA pipe (no MUFU): 2^(x*log2e) with deg-5 poly, |rel err| ~2e-6
__device__ __forceinline__ float fexp(float x) {
    x = fmaxf(x, -80.f);
    float t = x * 1.4426950408889634f;
    int   i = __float2int_rn(t);
    float f = t - (float)i;
    float p =             1.3333558e-3f;
    p = fmaf(p, f, 9.6181291e-3f);
    p = fmaf(p, f, 5.5504109e-2f);
    p = fmaf(p, f, 2.4022651e-1f);
    p = fmaf(p, f, 6.9314718e-1f);
    p = fmaf(p, f, 1.0f);
    return p * __int_as_float((i + 127) << 23);
}

#define CP_ASYNC16(dst, src) \
    asm volatile("cp.async.cg.shared.global [%0], [%1], 16;\n" :: "r"(dst), "l"(src))
#define CP_COMMIT() asm volatile("cp.async.commit_group;\n" ::: "memory")
#define CP_WAIT(n)  asm volatile("cp.async.wait_group %0;\n" :: "n"(n) : "memory")

__device__ __forceinline__ void ldsm4(uint32_t* r, uint32_t addr) {
    asm volatile("ldmatrix.sync.aligned.m8n8.x4.shared.b16 {%0,%1,%2,%3}, [%4];\n"
        : "=r"(r[0]), "=r"(r[1]), "=r"(r[2]), "=r"(r[3]) : "r"(addr));
}

__device__ __forceinline__ void mma16816(float* d, const uint32_t* a, const uint32_t* b) {
    asm volatile(
        "mma.sync.aligned.m16n8k16.row.col.f32.bf16.bf16.f32 "
        "{%0,%1,%2,%3}, {%4,%5,%6,%7}, {%8,%9}, {%0,%1,%2,%3};\n"
        : "+f"(d[0]), "+f"(d[1]), "+f"(d[2]), "+f"(d[3])
        : "r"(a[0]), "r"(a[1]), "r"(a[2]), "r"(a[3]), "r"(b[0]), "r"(b[1]));
}

// ---------------- embedding ----------------------------------------------------
__global__ void embed_kernel(const int* __restrict__ idx,
                             const float* __restrict__ wte,
                             const float* __restrict__ wpe) {
    int row = blockIdx.x;
    int t = row % TSEQ;
    int tok = idx[row];
    const float* we = wte + (size_t)tok * D;
    const float* wp = wpe + (size_t)t * D;
    float* out = g_x + (size_t)row * D;
    for (int d = threadIdx.x; d < D; d += blockDim.x)
        out[d] = we[d] + wp[d];
}

// ---------------- bf16 split helpers ------------------------------------------
__device__ __forceinline__ void split1(float x, __nv_bfloat16& h, __nv_bfloat16& l) {
    __nv_bfloat16 hh = __float2bfloat16_rn(x);
    h = hh;
    l = __float2bfloat16_rn(x - __bfloat162float(hh));
}

__global__ void split4_kernel(const float* __restrict__ in,
                              __nv_bfloat16* __restrict__ oh,
                              __nv_bfloat16* __restrict__ ol, int n4) {
    int i = blockIdx.x * blockDim.x + threadIdx.x;
    if (i < n4) {
        float4 v = reinterpret_cast<const float4*>(in)[i];
        __nv_bfloat16 h0, l0, h1, l1, h2, l2, h3, l3;
        split1(v.x, h0, l0); split1(v.y, h1, l1);
        split1(v.z, h2, l2); split1(v.w, h3, l3);
        __nv_bfloat162* ph = reinterpret_cast<__nv_bfloat162*>(oh + (size_t)i * 4);
        ph[0] = __halves2bfloat162(h0, h1);
        ph[1] = __halves2bfloat162(h2, h3);
        __nv_bfloat162* pl = reinterpret_cast<__nv_bfloat162*>(ol + (size_t)i * 4);
        pl[0] = __halves2bfloat162(l0, l1);
        pl[1] = __halves2bfloat162(l2, l3);
    }
}

// ---------------- layernorm fused with split ----------------------------------
__global__ void ln_split_kernel(const float* __restrict__ x,
                                const float* __restrict__ s,
                                const float* __restrict__ b,
                                __nv_bfloat16* __restrict__ oh,
                                __nv_bfloat16* __restrict__ ol) {
    int row = blockIdx.x;
    const float* xr = x + (size_t)row * D;
    float s1 = 0.f, s2 = 0.f;
    for (int d = threadIdx.x; d < D; d += blockDim.x) {
        float v = xr[d];
        s1 += v; s2 += v * v;
    }
    __shared__ float r1[8], r2[8];
    int lane = threadIdx.x & 31, w = threadIdx.x >> 5;
    s1 = warp_sum(s1); s2 = warp_sum(s2);
    if (lane == 0) { r1[w] = s1; r2[w] = s2; }
    __syncthreads();
    __shared__ float s_mean, s_inv;
    if (threadIdx.x == 0) {
        float t1 = 0.f, t2 = 0.f;
        #pragma unroll
        for (int i = 0; i < 8; i++) { t1 += r1[i]; t2 += r2[i]; }
        float m = t1 / (float)D;
        float var = t2 / (float)D - m * m;
        s_mean = m; s_inv = rsqrtf(var + 1e-5f);
    }
    __syncthreads();
    float m = s_mean, inv = s_inv;
    for (int d = threadIdx.x; d < D; d += blockDim.x) {
        float v = (xr[d] - m) * inv * s[d] + b[d];
        __nv_bfloat16 hh, ll;
        split1(v, hh, ll);
        oh[(size_t)row * D + d] = hh;
        ol[(size_t)row * D + d] = ll;
    }
}

// qkv weight pack + transpose + split
__global__ void qkv_pack_kernel(const float* __restrict__ Wq, const float* __restrict__ Wk,
                                const float* __restrict__ Wv,
                                const float* __restrict__ bq, const float* __restrict__ bk,
                                const float* __restrict__ bv) {
    int l = blockIdx.y;
    int i = blockIdx.x * blockDim.x + threadIdx.x;
    if (i < QKVN * D) {
        int n = i / D;
        int k = i - n * D;
        int sec = n / D;
        int r = n - sec * D;
        int h = r / HS, e = r - h * HS;
        const float* W = (sec == 0) ? Wq : (sec == 1) ? Wk : Wv;
        float v = W[(((size_t)l * NH + h) * D + k) * HS + e];
        __nv_bfloat16 hh, ll;
        split1(v, hh, ll);
        g_qkvwh[(size_t)l * QKVN * D + i] = hh;
        g_qkvwl[(size_t)l * QKVN * D + i] = ll;
    }
    if (i < QKVN) {
        int sec = i / D, r = i - sec * D;
        const float* bb = (sec == 0) ? bq : (sec == 1) ? bk : bv;
        g_bc2[l * QKVN + i] = bb[(size_t)l * D + r];
    }
}

// transpose + split: in [K,N] f32 -> out [N,K] hi/lo bf16
__global__ void tsplit_kernel(const float* __restrict__ in,
                              __nv_bfloat16* __restrict__ oh,
                              __nv_bfloat16* __restrict__ ol, int Kd, int Nd) {
    __shared__ float t[32][33];
    int n0 = blockIdx.x * 32, k0 = blockIdx.y * 32;
    int tx = threadIdx.x, ty = threadIdx.y;
    #pragma unroll
    for (int i = 0; i < 4; i++) {
        int k = k0 + ty + i * 8, n = n0 + tx;
        if (k < Kd && n < Nd) t[ty + i * 8][tx] = in[(size_t)k * Nd + n];
    }
    __syncthreads();
    #pragma unroll
    for (int i = 0; i < 4; i++) {
        int n = n0 + ty + i * 8, k = k0 + tx;
        if (n < Nd && k < Kd) {
            __nv_bfloat16 h, l;
            split1(t[tx][ty + i * 8], h, l);
            oh[(size_t)n * Kd + k] = h;
            ol[(size_t)n * Kd + k] = l;
        }
    }
}

__global__ void zero_rowsum_kernel() {
    int i = blockIdx.x * blockDim.x + threadIdx.x;
    if (i < ROWS) g_rowsum[i] = 0.f;
}

// ---------------- mma.sync bf16x3 GEMM ----------------------------------------
// 6 stages of 16-K chunks; one barrier per TWO chunks.
#define GSTAGES 6
#define STAGE_BYTES 24576
#define OFF_AH 0
#define OFF_AL 6144
#define OFF_BH 12288
#define OFF_BL 18432
#define GEMM_SMEM (GSTAGES * STAGE_BYTES)   // 147456

template<bool BIAS, bool RES, bool GELU, bool SPLIT, bool LACC>
__global__ __launch_bounds__(256)
void mma_gemm_kernel(const __nv_bfloat16* __restrict__ a_h, const __nv_bfloat16* __restrict__ a_l,
                     const __nv_bfloat16* __restrict__ b_h, const __nv_bfloat16* __restrict__ b_l,
                     const float* __restrict__ bias, const float* __restrict__ res,
                     float* __restrict__ C,
                     __nv_bfloat16* __restrict__ outh, __nv_bfloat16* __restrict__ outl,
                     int M, int N, int K) {
    extern __shared__ char dsm[];
    __shared__ float srow[128];
    const uint32_t smem = smem_u32(dsm);
    const int tid = threadIdx.x;
    const int m0 = blockIdx.x * 128;
    const int n0 = blockIdx.y * 128;
    const int lane = tid & 31, warp = tid >> 5;
    const int wm = warp >> 1, wn = warp & 1;

    const int grow = tid >> 1, half = tid & 1;
    const int brow = min(n0 + grow, N - 1);
    const uint32_t dst_off = (uint32_t)(grow * 48 + half * 16);
    const __nv_bfloat16* pah = a_h + (size_t)(m0 + grow) * K + half * 8;
    const __nv_bfloat16* pal = a_l + (size_t)(m0 + grow) * K + half * 8;
    const __nv_bfloat16* pbh = b_h + (size_t)brow * K + half * 8;
    const __nv_bfloat16* pbl = b_l + (size_t)brow * K + half * 8;

    const int nch = K >> 4;   // always even (K % 32 == 0 for all our shapes)

    float acc[2][8][4];
    #pragma unroll
    for (int i = 0; i < 2; i++)
        #pragma unroll
        for (int j = 0; j < 8; j++)
            #pragma unroll
            for (int u = 0; u < 4; u++) acc[i][j][u] = 0.f;

    // prologue: load 4 chunks (one commit group per chunk)
    #pragma unroll
    for (int s = 0; s < 4; ++s) {
        uint32_t sb = smem + (uint32_t)s * STAGE_BYTES;
        int k = s << 4;
        CP_ASYNC16(sb + OFF_AH + dst_off, pah + k);
        CP_ASYNC16(sb + OFF_AL + dst_off, pal + k);
        CP_ASYNC16(sb + OFF_BH + dst_off, pbh + k);
        CP_ASYNC16(sb + OFF_BL + dst_off, pbl + k);
        CP_COMMIT();
    }

    const uint32_t aoff = (uint32_t)((lane & 15) * 48 + (lane >> 4) * 16 + wm * 32 * 48);
    const uint32_t boff = (uint32_t)((((lane >> 4) * 8) + (lane & 7)) * 48 +
                                     ((lane >> 3) & 1) * 16 + wn * 64 * 48);

    for (int c = 0; c < nch; c += 2) {
        // wait for chunks c, c+1 (leave up to 2 groups in flight when more follow)
        if (c + 4 < nch) { CP_WAIT(2); } else { CP_WAIT(0); }
        __syncthreads();
        // prefetch chunks c+4, c+5
        #pragma unroll
        for (int u = 0; u < 2; ++u) {
            int s = c + 4 + u;
            if (s < nch) {
                uint32_t sb = smem + (uint32_t)(s % GSTAGES) * STAGE_BYTES;
                int k = s << 4;
                CP_ASYNC16(sb + OFF_AH + dst_off, pah + k);
                CP_ASYNC16(sb + OFF_AL + dst_off, pal + k);
                CP_ASYNC16(sb + OFF_BH + dst_off, pbh + k);
                CP_ASYNC16(sb + OFF_BL + dst_off, pbl + k);
                CP_COMMIT();
            }
        }
        // compute chunks c and c+1
        #pragma unroll
        for (int u = 0; u < 2; ++u) {
            uint32_t sb = smem + (uint32_t)((c + u) % GSTAGES) * STAGE_BYTES;
            uint32_t ah0[4], ah1[4], al0[4], al1[4], bhf[4][4], blf[4][4];
            ldsm4(ah0, sb + OFF_AH + aoff);
            ldsm4(ah1, sb + OFF_AH + aoff + 16 * 48);
            ldsm4(al0, sb + OFF_AL + aoff);
            ldsm4(al1, sb + OFF_AL + aoff + 16 * 48);
            #pragma unroll
            for (int j = 0; j < 4; ++j) {
                ldsm4(bhf[j], sb + OFF_BH + boff + (uint32_t)(j * 16 * 48));
                ldsm4(blf[j], sb + OFF_BL + boff + (uint32_t)(j * 16 * 48));
            }
            #pragma unroll
            for (int i = 0; i < 2; ++i) {
                const uint32_t* Ah = i ? ah1 : ah0;
                const uint32_t* Al = i ? al1 : al0;
                #pragma unroll
                for (int j = 0; j < 8; ++j) {
                    uint32_t bh2[2] = { bhf[j >> 1][(j & 1) * 2], bhf[j >> 1][(j & 1) * 2 + 1] };
                    uint32_t bl2[2] = { blf[j >> 1][(j & 1) * 2], blf[j >> 1][(j & 1) * 2 + 1] };
                    mma16816(acc[i][j], Ah, bh2);
                    mma16816(acc[i][j], Ah, bl2);
                    mma16816(acc[i][j], Al, bh2);
                }
            }
        }
    }

    // ---- epilogue: stage through smem, then coalesced output
    CP_WAIT(0);
    __syncthreads();
    float* stage = reinterpret_cast<float*>(dsm);   // [128][132] f32 = 67584B
    #pragma unroll
    for (int i = 0; i < 2; ++i)
        #pragma unroll
        for (int j = 0; j < 8; ++j) {
            int r = wm * 32 + i * 16 + (lane >> 2);
            int cc = wn * 64 + j * 8 + (lane & 3) * 2;
            stage[r * 132 + cc]           = acc[i][j][0];
            stage[r * 132 + cc + 1]       = acc[i][j][1];
            stage[(r + 8) * 132 + cc]     = acc[i][j][2];
            stage[(r + 8) * 132 + cc + 1] = acc[i][j][3];
        }
    if (LACC) {
        for (int i = tid; i < 128; i += 256) srow[i] = 0.f;
    }
    __syncthreads();
    for (int it = 0; it < 64; ++it) {
        int idx = it * 256 + tid;
        int r = idx >> 7, cc = idx & 127;
        int gn = n0 + cc;
        float e = 0.f;
        if (gn < N) {
            float v = stage[r * 132 + cc];
            if (BIAS) v += bias[gn];
            if (RES)  v += res[(size_t)(m0 + r) * N + gn];
            if (GELU) v = 0.5f * v * (1.0f + erff(v * 0.70710678118654752f));
            if (SPLIT) {
                __nv_bfloat16 hh, ll;
                split1(v, hh, ll);
                outh[(size_t)(m0 + r) * N + gn] = hh;
                outl[(size_t)(m0 + r) * N + gn] = ll;
            } else {
                C[(size_t)(m0 + r) * N + gn] = v;
            }
            if (LACC) e = fexp(v);
        }
        if (LACC) {
            e = warp_sum(e);
            if (lane == 0) atomicAdd(&srow[r], e);
        }
    }
    if (LACC) {
        __syncthreads();
        for (int i = tid; i < 128; i += 256)
            atomicAdd(&g_rowsum[m0 + i], srow[i]);
    }
}

// ---------------- flash attention (64-q tile per block) -----------------------
#define AT_STRIDE 76
#define ATTN_SMEM (4 * 64 * AT_STRIDE * 4)   // 77824 bytes

__global__ __launch_bounds__(256)
void attn_flash_kernel(__nv_bfloat16* __restrict__ oh, __nv_bfloat16* __restrict__ ol) {
    extern __shared__ float sm[];
    float* Qs = sm;                          // [64][76]
    float* Ks = Qs + 64 * AT_STRIDE;
    float* Vs = Ks + 64 * AT_STRIDE;
    float* Ps = Vs + 64 * AT_STRIDE;         // [k][r] layout

    const int qt = blockIdx.x;
    const int bh = blockIdx.y;
    const int b = bh / NH, h = bh % NH;
    const int tid = threadIdx.x;
    const int qg = tid >> 4;
    const int kg = tid & 15;
    const int q0 = qt * 64;
    const size_t base = (size_t)b * TSEQ * QKVN;

    #pragma unroll
    for (int i = 0; i < 4; ++i) {
        int f = tid + i * 256;
        int row = f >> 4, c4 = f & 15;
        *reinterpret_cast<float4*>(&Qs[row * AT_STRIDE + c4 * 4]) =
            *reinterpret_cast<const float4*>(&g_qkv[base + (size_t)(q0 + row) * QKVN + h * HS + c4 * 4]);
    }

    float acc[4][4];
    #pragma unroll
    for (int i = 0; i < 4; ++i)
        #pragma unroll
        for (int j = 0; j < 4; ++j) acc[i][j] = 0.f;
    float row_m[4] = {-1e30f, -1e30f, -1e30f, -1e30f};
    float row_l[4] = {0.f, 0.f, 0.f, 0.f};

    for (int t = 0; t <= qt; ++t) {
        __syncthreads();
        #pragma unroll
        for (int i = 0; i < 4; ++i) {
            int f = tid + i * 256;
            int row = f >> 4, c4 = f & 15;
            size_t g = base + (size_t)(t * 64 + row) * QKVN + h * HS + c4 * 4;
            *reinterpret_cast<float4*>(&Ks[row * AT_STRIDE + c4 * 4]) =
                *reinterpret_cast<const float4*>(&g_qkv[g + D]);
            *reinterpret_cast<float4*>(&Vs[row * AT_STRIDE + c4 * 4]) =
                *reinterpret_cast<const float4*>(&g_qkv[g + 2 * D]);
        }
        __syncthreads();

        float dp[4][4];
        #pragma unroll
        for (int i = 0; i < 4; ++i)
            #pragma unroll
            for (int j = 0; j < 4; ++j) dp[i][j] = 0.f;
        #pragma unroll
        for (int e4 = 0; e4 < 16; ++e4) {
            float4 qv[4], kv[4];
            #pragma unroll
            for (int i = 0; i < 4; ++i)
                qv[i] = *reinterpret_cast<const float4*>(&Qs[(qg * 4 + i) * AT_STRIDE + e4 * 4]);
            #pragma unroll
            for (int j = 0; j < 4; ++j)
                kv[j] = *reinterpret_cast<const float4*>(&Ks[(kg * 4 + j) * AT_STRIDE + e4 * 4]);
            #pragma unroll
            for (int i = 0; i < 4; ++i)
                #pragma unroll
                for (int j = 0; j < 4; ++j)
                    dp[i][j] = fmaf(qv[i].x, kv[j].x, fmaf(qv[i].y, kv[j].y,
                               fmaf(qv[i].z, kv[j].z, fmaf(qv[i].w, kv[j].w, dp[i][j]))));
        }

        const bool diag = (t == qt);
        float p[4][4];
        #pragma unroll
        for (int i = 0; i < 4; ++i) {
            int rglob = qg * 4 + i;
            float tm = -1e30f;
            #pragma unroll
            for (int j = 0; j < 4; ++j) {
                bool valid = !diag || (kg * 4 + j <= rglob);
                float sv = valid ? dp[i][j] : -1e30f;
                dp[i][j] = sv;
                tm = fmaxf(tm, sv);
            }
            #pragma unroll
            for (int o = 1; o < 16; o <<= 1)
                tm = fmaxf(tm, __shfl_xor_sync(0xffffffffu, tm, o));
            float newm = fmaxf(row_m[i], tm);
            float corr = fexp(row_m[i] - newm);
            row_m[i] = newm;
            float ts = 0.f;
            #pragma unroll
            for (int j = 0; j < 4; ++j) {
                float pv = (dp[i][j] > -1e29f) ? fexp(dp[i][j] - newm) : 0.f;
                p[i][j] = pv;
                ts += pv;
            }
            #pragma unroll
            for (int o = 1; o < 16; o <<= 1)
                ts += __shfl_xor_sync(0xffffffffu, ts, o);
            row_l[i] = row_l[i] * corr + ts;
            #pragma unroll
            for (int j = 0; j < 4; ++j) acc[i][j] *= corr;
        }

        #pragma unroll
        for (int i = 0; i < 4; ++i)
            #pragma unroll
            for (int j = 0; j < 4; ++j)
                Ps[(kg * 4 + j) * AT_STRIDE + qg * 4 + i] = p[i][j];
        __syncthreads();

        for (int k = 0; k < 64; ++k) {
            float4 pv = *reinterpret_cast<const float4*>(&Ps[k * AT_STRIDE + qg * 4]);
            float4 vv = *reinterpret_cast<const float4*>(&Vs[k * AT_STRIDE + kg * 4]);
            float pr[4] = {pv.x, pv.y, pv.z, pv.w};
            float vr[4] = {vv.x, vv.y, vv.z, vv.w};
            #pragma unroll
            for (int i = 0; i < 4; ++i)
                #pragma unroll
                for (int j = 0; j < 4; ++j)
                    acc[i][j] = fmaf(pr[i], vr[j], acc[i][j]);
        }
    }

    #pragma unroll
    for (int i = 0; i < 4; ++i) {
        float sc = 0.125f / row_l[i];
        size_t orow = ((size_t)(b * TSEQ + q0 + qg * 4 + i)) * D + h * HS + kg * 4;
        #pragma unroll
        for (int j = 0; j < 4; ++j) {
            __nv_bfloat16 hh, ll;
            split1(acc[i][j] * sc, hh, ll);
            oh[orow + j] = hh;
            ol[orow + j] = ll;
        }
    }
}

// ---------------- loss ---------------------------------------------------------
__global__ void loss_final_kernel(const float* __restrict__ logits,
                                  const int* __restrict__ targets,
                                  float* __restrict__ d_out, int out_size) {
    int tid = threadIdx.x, lane = tid & 31, w = tid >> 5;
    float s = 0.f;
    for (int row = tid; row < ROWS; row += blockDim.x) {
        float ls = logf(g_rowsum[row]);
        s += ls - logits[(size_t)row * VOCAB + targets[row]];
    }
    __shared__ float r[8];
    s = warp_sum(s);
    if (lane == 0) r[w] = s;
    __syncthreads();
    if (tid == 0) {
        float t = 0.f;
        #pragma unroll
        for (int i = 0; i < 8; i++) t += r[i];
        float loss = t / (float)ROWS;
        size_t btv = (size_t)ROWS * VOCAB;
        if ((size_t)out_size > btv) d_out[btv] = loss;
    }
}

// ---------------- driver -------------------------------------------------------
template<bool BIAS, bool RES, bool GELU, bool SPLIT, bool LACC>
static void tc_gemm(const __nv_bfloat16* ah, const __nv_bfloat16* al,
                    const __nv_bfloat16* bh, const __nv_bfloat16* bl,
                    const float* bias, const float* res, float* C,
                    __nv_bfloat16* outh, __nv_bfloat16* outl,
                    int M, int N, int K) {
    cudaFuncSetAttribute(mma_gemm_kernel<BIAS, RES, GELU, SPLIT, LACC>,
                         cudaFuncAttributeMaxDynamicSharedMemorySize, GEMM_SMEM);
    dim3 grid(M / 128, (N + 127) / 128);
    mma_gemm_kernel<BIAS, RES, GELU, SPLIT, LACC><<<grid, 256, GEMM_SMEM>>>(
        ah, al, bh, bl, bias, res, C, outh, outl, M, N, K);
}

extern "C" void kernel_launch(void* const* d_in, const int* in_sizes, int n_in,
                              void* d_out, int out_size) {
    const int*   idx     = (const int*)  d_in[0];
    const int*   targets = (const int*)  d_in[1];
    const float* wte     = (const float*)d_in[2];
    const float* wpe     = (const float*)d_in[3];
    const float* ln1_s   = (const float*)d_in[4];
    const float* ln1_b   = (const float*)d_in[5];
    const float* ln2_s   = (const float*)d_in[6];
    const float* ln2_b   = (const float*)d_in[7];
    const float* Wq      = (const float*)d_in[8];
    const float* bq      = (const float*)d_in[9];
    const float* Wk      = (const float*)d_in[10];
    const float* bk      = (const float*)d_in[11];
    const float* Wv      = (const float*)d_in[12];
    const float* bv      = (const float*)d_in[13];
    const float* Wo      = (const float*)d_in[14];
    const float* bo      = (const float*)d_in[15];
    const float* W1      = (const float*)d_in[16];
    const float* b1      = (const float*)d_in[17];
    const float* W2      = (const float*)d_in[18];
    const float* b2      = (const float*)d_in[19];
    const float* lnf_s   = (const float*)d_in[20];
    const float* lnf_b   = (const float*)d_in[21];

    float* out = (float*)d_out;

    float *gx, *gqkv, *gbc;
    __nv_bfloat16 *ah, *al, *ah2, *al2, *wteh, *wtel, *qkvwh, *qkvwl, *woh, *wol, *w1h, *w1l, *w2h, *w2l;
    cudaGetSymbolAddress((void**)&gx,   g_x);
    cudaGetSymbolAddress((void**)&gqkv, g_qkv);
    cudaGetSymbolAddress((void**)&gbc,  g_bc2);
    cudaGetSymbolAddress((void**)&ah,   g_ah);
    cudaGetSymbolAddress((void**)&al,   g_al);
    cudaGetSymbolAddress((void**)&ah2,  g_ah2);
    cudaGetSymbolAddress((void**)&al2,  g_al2);
    cudaGetSymbolAddress((void**)&wteh, g_wteh);
    cudaGetSymbolAddress((void**)&wtel, g_wtel);
    cudaGetSymbolAddress((void**)&qkvwh, g_qkvwh);
    cudaGetSymbolAddress((void**)&qkvwl, g_qkvwl);
    cudaGetSymbolAddress((void**)&woh,  g_woh);
    cudaGetSymbolAddress((void**)&wol,  g_wol);
    cudaGetSymbolAddress((void**)&w1h,  g_w1h);
    cudaGetSymbolAddress((void**)&w1l,  g_w1l);
    cudaGetSymbolAddress((void**)&w2h,  g_w2h);
    cudaGetSymbolAddress((void**)&w2l,  g_w2l);

    // ---- weight prep ----
    {
        dim3 b(256), g((QKVN * D + 255) / 256, LAYERS);
        qkv_pack_kernel<<<g, b>>>(Wq, Wk, Wv, bq, bk, bv);
    }
    for (int l = 0; l < LAYERS; l++) {
        dim3 blk(32, 8);
        tsplit_kernel<<<dim3(D / 32, D / 32), blk>>>(Wo + (size_t)l * D * D,
            woh + (size_t)l * D * D, wol + (size_t)l * D * D, D, D);
        tsplit_kernel<<<dim3(FF / 32, D / 32), blk>>>(W1 + (size_t)l * D * FF,
            w1h + (size_t)l * FF * D, w1l + (size_t)l * FF * D, D, FF);
        tsplit_kernel<<<dim3(D / 32, FF / 32), blk>>>(W2 + (size_t)l * FF * D,
            w2h + (size_t)l * D * FF, w2l + (size_t)l * D * FF, FF, D);
    }
    split4_kernel<<<(VOCAB * D / 4 + 255) / 256, 256>>>(wte, wteh, wtel, VOCAB * D / 4);
    zero_rowsum_kernel<<<8, 256>>>();

    embed_kernel<<<ROWS, 256>>>(idx, wte, wpe);

    cudaFuncSetAttribute(attn_flash_kernel,
                         cudaFuncAttributeMaxDynamicSharedMemorySize, ATTN_SMEM);

    for (int l = 0; l < LAYERS; l++) {
        ln_split_kernel<<<ROWS, 256>>>(gx, ln1_s + (size_t)l * D, ln1_b + (size_t)l * D, ah, al);
        tc_gemm<true, false, false, false, false>(ah, al,
            qkvwh + (size_t)l * QKVN * D, qkvwl + (size_t)l * QKVN * D,
            gbc + l * QKVN, nullptr, gqkv, nullptr, nullptr, ROWS, QKVN, D);

        attn_flash_kernel<<<dim3(TSEQ / 64, BATCH * NH), 256, ATTN_SMEM>>>(ah, al);

        tc_gemm<true, true, false, false, false>(ah, al,
            woh + (size_t)l * D * D, wol + (size_t)l * D * D,
            bo + (size_t)l * D, gx, gx, nullptr, nullptr, ROWS, D, D);

        ln_split_kernel<<<ROWS, 256>>>(gx, ln2_s + (size_t)l * D, ln2_b + (size_t)l * D, ah, al);
        tc_gemm<true, false, true, true, false>(ah, al,
            w1h + (size_t)l * FF * D, w1l + (size_t)l * FF * D,
            b1 + (size_t)l * FF, nullptr, nullptr, ah2, al2, ROWS, FF, D);

        tc_gemm<true, true, false, false, false>(ah2, al2,
            w2h + (size_t)l * D * FF, w2l + (size_t)l * D * FF,
            b2 + (size_t)l * D, gx, gx, nullptr, nullptr, ROWS, D, FF);
    }

    ln_split_kernel<<<ROWS, 256>>>(gx, lnf_s, lnf_b, ah, al);
    // logits = h @ wte^T with fused exp-rowsum accumulation
    tc_gemm<false, false, false, false, true>(ah, al, wteh, wtel,
        nullptr, nullptr, out, nullptr, nullptr, ROWS, VOCAB, D);

    loss_final_kernel<<<1, 256>>>(out, targets, out, out_size);
}

// round 12
// speedup vs baseline: 1.1688x; 1.1688x over previous
#include <cuda_runtime.h>
#include <cuda_bf16.h>
#include <math.h>
#include <stdint.h>

// Problem constants
#define LAYERS 2
#define NH     12
#define D      768
#define HS     64
#define FF     3072
#define VOCAB  50257
#define BATCH  4
#define TSEQ   512
#define ROWS   (BATCH * TSEQ)       // 2048
#define QKVN   (3 * D)              // 2304

// ---------------- scratch (static device globals; no allocation) --------------
__device__ float g_x[ROWS * D];
__device__ float g_qkv[ROWS * QKVN];
__device__ float g_rowsum[ROWS];
__device__ float g_bc2[LAYERS * QKVN];

// bf16 split operands
__device__ __nv_bfloat16 g_ah[ROWS * D];
__device__ __nv_bfloat16 g_al[ROWS * D];
__device__ __nv_bfloat16 g_ah2[ROWS * FF];
__device__ __nv_bfloat16 g_al2[ROWS * FF];
__device__ __nv_bfloat16 g_wteh[VOCAB * D];
__device__ __nv_bfloat16 g_wtel[VOCAB * D];
__device__ __nv_bfloat16 g_qkvwh[LAYERS * QKVN * D];
__device__ __nv_bfloat16 g_qkvwl[LAYERS * QKVN * D];
__device__ __nv_bfloat16 g_woh[LAYERS * D * D];
__device__ __nv_bfloat16 g_wol[LAYERS * D * D];
__device__ __nv_bfloat16 g_w1h[LAYERS * FF * D];
__device__ __nv_bfloat16 g_w1l[LAYERS * FF * D];
__device__ __nv_bfloat16 g_w2h[LAYERS * D * FF];
__device__ __nv_bfloat16 g_w2l[LAYERS * D * FF];

// ---------------- small helpers ----------------------------------------------
__device__ __forceinline__ float warp_sum(float v) {
    #pragma unroll
    for (int o = 16; o > 0; o >>= 1) v += __shfl_xor_sync(0xffffffffu, v, o);
    return v;
}

__device__ __forceinline__ uint32_t smem_u32(const void* p) {
    uint32_t a;
    asm("{ .reg .u64 t; cvta.to.shared.u64 t, %1; cvt.u32.u64 %0, t; }" : "=r"(a) : "l"(p));
    return a;
}

// fast exp on the FMA pipe (no MUFU): 2^(x*log2e) with deg-5 poly, |rel err| ~2e-6
__device__ __forceinline__ float fexp(float x) {
    x = fmaxf(x, -80.f);
    float t = x * 1.4426950408889634f;
    int   i = __float2int_rn(t);
    float f = t - (float)i;
    float p =             1.3333558e-3f;
    p = fmaf(p, f, 9.6181291e-3f);
    p = fmaf(p, f, 5.5504109e-2f);
    p = fmaf(p, f, 2.4022651e-1f);
    p = fmaf(p, f, 6.9314718e-1f);
    p = fmaf(p, f, 1.0f);
    return p * __int_as_float((i + 127) << 23);
}

#define CP_ASYNC16(dst, src) \
    asm volatile("cp.async.cg.shared.global [%0], [%1], 16;\n" :: "r"(dst), "l"(src))
#define CP_COMMIT() asm volatile("cp.async.commit_group;\n" ::: "memory")
#define CP_WAIT(n)  asm volatile("cp.async.wait_group %0;\n" :: "n"(n) : "memory")

__device__ __forceinline__ void ldsm4(uint32_t* r, uint32_t addr) {
    asm volatile("ldmatrix.sync.aligned.m8n8.x4.shared.b16 {%0,%1,%2,%3}, [%4];\n"
        : "=r"(r[0]), "=r"(r[1]), "=r"(r[2]), "=r"(r[3]) : "r"(addr));
}

__device__ __forceinline__ void mma16816(float* d, const uint32_t* a, const uint32_t* b) {
    asm volatile(
        "mma.sync.aligned.m16n8k16.row.col.f32.bf16.bf16.f32 "
        "{%0,%1,%2,%3}, {%4,%5,%6,%7}, {%8,%9}, {%0,%1,%2,%3};\n"
        : "+f"(d[0]), "+f"(d[1]), "+f"(d[2]), "+f"(d[3])
        : "r"(a[0]), "r"(a[1]), "r"(a[2]), "r"(a[3]), "r"(b[0]), "r"(b[1]));
}

// ---------------- embedding ----------------------------------------------------
__global__ void embed_kernel(const int* __restrict__ idx,
                             const float* __restrict__ wte,
                             const float* __restrict__ wpe) {
    int row = blockIdx.x;
    int t = row % TSEQ;
    int tok = idx[row];
    const float* we = wte + (size_t)tok * D;
    const float* wp = wpe + (size_t)t * D;
    float* out = g_x + (size_t)row * D;
    for (int d = threadIdx.x; d < D; d += blockDim.x)
        out[d] = we[d] + wp[d];
}

// ---------------- bf16 split helpers ------------------------------------------
__device__ __forceinline__ void split1(float x, __nv_bfloat16& h, __nv_bfloat16& l) {
    __nv_bfloat16 hh = __float2bfloat16_rn(x);
    h = hh;
    l = __float2bfloat16_rn(x - __bfloat162float(hh));
}

__global__ void split4_kernel(const float* __restrict__ in,
                              __nv_bfloat16* __restrict__ oh,
                              __nv_bfloat16* __restrict__ ol, int n4) {
    int i = blockIdx.x * blockDim.x + threadIdx.x;
    if (i < n4) {
        float4 v = reinterpret_cast<const float4*>(in)[i];
        __nv_bfloat16 h0, l0, h1, l1, h2, l2, h3, l3;
        split1(v.x, h0, l0); split1(v.y, h1, l1);
        split1(v.z, h2, l2); split1(v.w, h3, l3);
        __nv_bfloat162* ph = reinterpret_cast<__nv_bfloat162*>(oh + (size_t)i * 4);
        ph[0] = __halves2bfloat162(h0, h1);
        ph[1] = __halves2bfloat162(h2, h3);
        __nv_bfloat162* pl = reinterpret_cast<__nv_bfloat162*>(ol + (size_t)i * 4);
        pl[0] = __halves2bfloat162(l0, l1);
        pl[1] = __halves2bfloat162(l2, l3);
    }
}

// ---------------- layernorm fused with split ----------------------------------
__global__ void ln_split_kernel(const float* __restrict__ x,
                                const float* __restrict__ s,
                                const float* __restrict__ b,
                                __nv_bfloat16* __restrict__ oh,
                                __nv_bfloat16* __restrict__ ol) {
    int row = blockIdx.x;
    const float* xr = x + (size_t)row * D;
    float s1 = 0.f, s2 = 0.f;
    for (int d = threadIdx.x; d < D; d += blockDim.x) {
        float v = xr[d];
        s1 += v; s2 += v * v;
    }
    __shared__ float r1[8], r2[8];
    int lane = threadIdx.x & 31, w = threadIdx.x >> 5;
    s1 = warp_sum(s1); s2 = warp_sum(s2);
    if (lane == 0) { r1[w] = s1; r2[w] = s2; }
    __syncthreads();
    __shared__ float s_mean, s_inv;
    if (threadIdx.x == 0) {
        float t1 = 0.f, t2 = 0.f;
        #pragma unroll
        for (int i = 0; i < 8; i++) { t1 += r1[i]; t2 += r2[i]; }
        float m = t1 / (float)D;
        float var = t2 / (float)D - m * m;
        s_mean = m; s_inv = rsqrtf(var + 1e-5f);
    }
    __syncthreads();
    float m = s_mean, inv = s_inv;
    for (int d = threadIdx.x; d < D; d += blockDim.x) {
        float v = (xr[d] - m) * inv * s[d] + b[d];
        __nv_bfloat16 hh, ll;
        split1(v, hh, ll);
        oh[(size_t)row * D + d] = hh;
        ol[(size_t)row * D + d] = ll;
    }
}

// qkv weight pack + transpose + split
__global__ void qkv_pack_kernel(const float* __restrict__ Wq, const float* __restrict__ Wk,
                                const float* __restrict__ Wv,
                                const float* __restrict__ bq, const float* __restrict__ bk,
                                const float* __restrict__ bv) {
    int l = blockIdx.y;
    int i = blockIdx.x * blockDim.x + threadIdx.x;
    if (i < QKVN * D) {
        int n = i / D;
        int k = i - n * D;
        int sec = n / D;
        int r = n - sec * D;
        int h = r / HS, e = r - h * HS;
        const float* W = (sec == 0) ? Wq : (sec == 1) ? Wk : Wv;
        float v = W[(((size_t)l * NH + h) * D + k) * HS + e];
        __nv_bfloat16 hh, ll;
        split1(v, hh, ll);
        g_qkvwh[(size_t)l * QKVN * D + i] = hh;
        g_qkvwl[(size_t)l * QKVN * D + i] = ll;
    }
    if (i < QKVN) {
        int sec = i / D, r = i - sec * D;
        const float* bb = (sec == 0) ? bq : (sec == 1) ? bk : bv;
        g_bc2[l * QKVN + i] = bb[(size_t)l * D + r];
    }
}

// transpose + split: in [K,N] f32 -> out [N,K] hi/lo bf16
__global__ void tsplit_kernel(const float* __restrict__ in,
                              __nv_bfloat16* __restrict__ oh,
                              __nv_bfloat16* __restrict__ ol, int Kd, int Nd) {
    __shared__ float t[32][33];
    int n0 = blockIdx.x * 32, k0 = blockIdx.y * 32;
    int tx = threadIdx.x, ty = threadIdx.y;
    #pragma unroll
    for (int i = 0; i < 4; i++) {
        int k = k0 + ty + i * 8, n = n0 + tx;
        if (k < Kd && n < Nd) t[ty + i * 8][tx] = in[(size_t)k * Nd + n];
    }
    __syncthreads();
    #pragma unroll
    for (int i = 0; i < 4; i++) {
        int n = n0 + ty + i * 8, k = k0 + tx;
        if (n < Nd && k < Kd) {
            __nv_bfloat16 h, l;
            split1(t[tx][ty + i * 8], h, l);
            oh[(size_t)n * Kd + k] = h;
            ol[(size_t)n * Kd + k] = l;
        }
    }
}

__global__ void zero_rowsum_kernel() {
    int i = blockIdx.x * blockDim.x + threadIdx.x;
    if (i < ROWS) g_rowsum[i] = 0.f;
}

// ---------------- mma.sync bf16x3 GEMM (R9 configuration: 3 stages) -----------
#define GSTAGES 3
#define STAGE_BYTES 24576
#define OFF_AH 0
#define OFF_AL 6144
#define OFF_BH 12288
#define OFF_BL 18432
#define GEMM_SMEM (GSTAGES * STAGE_BYTES)   // 73728

template<bool BIAS, bool RES, bool GELU, bool SPLIT, bool LACC>
__global__ __launch_bounds__(256)
void mma_gemm_kernel(const __nv_bfloat16* __restrict__ a_h, const __nv_bfloat16* __restrict__ a_l,
                     const __nv_bfloat16* __restrict__ b_h, const __nv_bfloat16* __restrict__ b_l,
                     const float* __restrict__ bias, const float* __restrict__ res,
                     float* __restrict__ C,
                     __nv_bfloat16* __restrict__ outh, __nv_bfloat16* __restrict__ outl,
                     int M, int N, int K) {
    extern __shared__ char dsm[];
    __shared__ float srow[128];
    const uint32_t smem = smem_u32(dsm);
    const int tid = threadIdx.x;
    const int m0 = blockIdx.x * 128;
    const int n0 = blockIdx.y * 128;
    const int lane = tid & 31, warp = tid >> 5;
    const int wm = warp >> 1, wn = warp & 1;

    const int grow = tid >> 1, half = tid & 1;
    const int brow = min(n0 + grow, N - 1);
    const uint32_t dst_off = (uint32_t)(grow * 48 + half * 16);
    const __nv_bfloat16* pah = a_h + (size_t)(m0 + grow) * K + half * 8;
    const __nv_bfloat16* pal = a_l + (size_t)(m0 + grow) * K + half * 8;
    const __nv_bfloat16* pbh = b_h + (size_t)brow * K + half * 8;
    const __nv_bfloat16* pbl = b_l + (size_t)brow * K + half * 8;

    const int nch = K >> 4;

    float acc[2][8][4];
    #pragma unroll
    for (int i = 0; i < 2; i++)
        #pragma unroll
        for (int j = 0; j < 8; j++)
            #pragma unroll
            for (int u = 0; u < 4; u++) acc[i][j][u] = 0.f;

    #pragma unroll
    for (int s = 0; s < GSTAGES - 1; ++s) {
        uint32_t sb = smem + (uint32_t)s * STAGE_BYTES;
        int k = s << 4;
        CP_ASYNC16(sb + OFF_AH + dst_off, pah + k);
        CP_ASYNC16(sb + OFF_AL + dst_off, pal + k);
        CP_ASYNC16(sb + OFF_BH + dst_off, pbh + k);
        CP_ASYNC16(sb + OFF_BL + dst_off, pbl + k);
        CP_COMMIT();
    }

    const uint32_t aoff = (uint32_t)((lane & 15) * 48 + (lane >> 4) * 16 + wm * 32 * 48);
    const uint32_t boff = (uint32_t)((((lane >> 4) * 8) + (lane & 7)) * 48 +
                                     ((lane >> 3) & 1) * 16 + wn * 64 * 48);

    for (int c = 0; c < nch; ++c) {
        CP_WAIT(GSTAGES - 2);
        __syncthreads();
        if (c + GSTAGES - 1 < nch) {
            int s = c + GSTAGES - 1;
            uint32_t sb = smem + (uint32_t)(s % GSTAGES) * STAGE_BYTES;
            int k = s << 4;
            CP_ASYNC16(sb + OFF_AH + dst_off, pah + k);
            CP_ASYNC16(sb + OFF_AL + dst_off, pal + k);
            CP_ASYNC16(sb + OFF_BH + dst_off, pbh + k);
            CP_ASYNC16(sb + OFF_BL + dst_off, pbl + k);
            CP_COMMIT();
        }
        uint32_t sb = smem + (uint32_t)(c % GSTAGES) * STAGE_BYTES;

        uint32_t ah0[4], ah1[4], al0[4], al1[4], bhf[4][4], blf[4][4];
        ldsm4(ah0, sb + OFF_AH + aoff);
        ldsm4(ah1, sb + OFF_AH + aoff + 16 * 48);
        ldsm4(al0, sb + OFF_AL + aoff);
        ldsm4(al1, sb + OFF_AL + aoff + 16 * 48);
        #pragma unroll
        for (int j = 0; j < 4; ++j) {
            ldsm4(bhf[j], sb + OFF_BH + boff + (uint32_t)(j * 16 * 48));
            ldsm4(blf[j], sb + OFF_BL + boff + (uint32_t)(j * 16 * 48));
        }
        #pragma unroll
        for (int i = 0; i < 2; ++i) {
            const uint32_t* Ah = i ? ah1 : ah0;
            const uint32_t* Al = i ? al1 : al0;
            #pragma unroll
            for (int j = 0; j < 8; ++j) {
                uint32_t bh2[2] = { bhf[j >> 1][(j & 1) * 2], bhf[j >> 1][(j & 1) * 2 + 1] };
                uint32_t bl2[2] = { blf[j >> 1][(j & 1) * 2], blf[j >> 1][(j & 1) * 2 + 1] };
                mma16816(acc[i][j], Ah, bh2);
                mma16816(acc[i][j], Ah, bl2);
                mma16816(acc[i][j], Al, bh2);
            }
        }
    }

    // ---- epilogue: stage through smem, then coalesced output
    CP_WAIT(0);
    __syncthreads();
    float* stage = reinterpret_cast<float*>(dsm);   // [128][132] f32 = 67584B
    #pragma unroll
    for (int i = 0; i < 2; ++i)
        #pragma unroll
        for (int j = 0; j < 8; ++j) {
            int r = wm * 32 + i * 16 + (lane >> 2);
            int cc = wn * 64 + j * 8 + (lane & 3) * 2;
            stage[r * 132 + cc]           = acc[i][j][0];
            stage[r * 132 + cc + 1]       = acc[i][j][1];
            stage[(r + 8) * 132 + cc]     = acc[i][j][2];
            stage[(r + 8) * 132 + cc + 1] = acc[i][j][3];
        }
    if (LACC) {
        for (int i = tid; i < 128; i += 256) srow[i] = 0.f;
    }
    __syncthreads();
    for (int it = 0; it < 64; ++it) {
        int idx = it * 256 + tid;
        int r = idx >> 7, cc = idx & 127;
        int gn = n0 + cc;
        float e = 0.f;
        if (gn < N) {
            float v = stage[r * 132 + cc];
            if (BIAS) v += bias[gn];
            if (RES)  v += res[(size_t)(m0 + r) * N + gn];
            if (GELU) v = 0.5f * v * (1.0f + erff(v * 0.70710678118654752f));
            if (SPLIT) {
                __nv_bfloat16 hh, ll;
                split1(v, hh, ll);
                outh[(size_t)(m0 + r) * N + gn] = hh;
                outl[(size_t)(m0 + r) * N + gn] = ll;
            } else {
                C[(size_t)(m0 + r) * N + gn] = v;
            }
            if (LACC) e = fexp(v);
        }
        if (LACC) {
            e = warp_sum(e);
            if (lane == 0) atomicAdd(&srow[r], e);
        }
    }
    if (LACC) {
        __syncthreads();
        for (int i = tid; i < 128; i += 256)
            atomicAdd(&g_rowsum[m0 + i], srow[i]);
    }
}

// ---------------- flash attention (64-q tile per block) -----------------------
#define AT_STRIDE 76
#define ATTN_SMEM (4 * 64 * AT_STRIDE * 4)   // 77824 bytes

__global__ __launch_bounds__(256)
void attn_flash_kernel(__nv_bfloat16* __restrict__ oh, __nv_bfloat16* __restrict__ ol) {
    extern __shared__ float sm[];
    float* Qs = sm;                          // [64][76]
    float* Ks = Qs + 64 * AT_STRIDE;
    float* Vs = Ks + 64 * AT_STRIDE;
    float* Ps = Vs + 64 * AT_STRIDE;         // [k][r] layout

    const int qt = blockIdx.x;
    const int bh = blockIdx.y;
    const int b = bh / NH, h = bh % NH;
    const int tid = threadIdx.x;
    const int qg = tid >> 4;
    const int kg = tid & 15;
    const int q0 = qt * 64;
    const size_t base = (size_t)b * TSEQ * QKVN;

    #pragma unroll
    for (int i = 0; i < 4; ++i) {
        int f = tid + i * 256;
        int row = f >> 4, c4 = f & 15;
        *reinterpret_cast<float4*>(&Qs[row * AT_STRIDE + c4 * 4]) =
            *reinterpret_cast<const float4*>(&g_qkv[base + (size_t)(q0 + row) * QKVN + h * HS + c4 * 4]);
    }

    float acc[4][4];
    #pragma unroll
    for (int i = 0; i < 4; ++i)
        #pragma unroll
        for (int j = 0; j < 4; ++j) acc[i][j] = 0.f;
    float row_m[4] = {-1e30f, -1e30f, -1e30f, -1e30f};
    float row_l[4] = {0.f, 0.f, 0.f, 0.f};

    for (int t = 0; t <= qt; ++t) {
        __syncthreads();
        #pragma unroll
        for (int i = 0; i < 4; ++i) {
            int f = tid + i * 256;
            int row = f >> 4, c4 = f & 15;
            size_t g = base + (size_t)(t * 64 + row) * QKVN + h * HS + c4 * 4;
            *reinterpret_cast<float4*>(&Ks[row * AT_STRIDE + c4 * 4]) =
                *reinterpret_cast<const float4*>(&g_qkv[g + D]);
            *reinterpret_cast<float4*>(&Vs[row * AT_STRIDE + c4 * 4]) =
                *reinterpret_cast<const float4*>(&g_qkv[g + 2 * D]);
        }
        __syncthreads();

        float dp[4][4];
        #pragma unroll
        for (int i = 0; i < 4; ++i)
            #pragma unroll
            for (int j = 0; j < 4; ++j) dp[i][j] = 0.f;
        #pragma unroll
        for (int e4 = 0; e4 < 16; ++e4) {
            float4 qv[4], kv[4];
            #pragma unroll
            for (int i = 0; i < 4; ++i)
                qv[i] = *reinterpret_cast<const float4*>(&Qs[(qg * 4 + i) * AT_STRIDE + e4 * 4]);
            #pragma unroll
            for (int j = 0; j < 4; ++j)
                kv[j] = *reinterpret_cast<const float4*>(&Ks[(kg * 4 + j) * AT_STRIDE + e4 * 4]);
            #pragma unroll
            for (int i = 0; i < 4; ++i)
                #pragma unroll
                for (int j = 0; j < 4; ++j)
                    dp[i][j] = fmaf(qv[i].x, kv[j].x, fmaf(qv[i].y, kv[j].y,
                               fmaf(qv[i].z, kv[j].z, fmaf(qv[i].w, kv[j].w, dp[i][j]))));
        }

        const bool diag = (t == qt);
        float p[4][4];
        #pragma unroll
        for (int i = 0; i < 4; ++i) {
            int rglob = qg * 4 + i;
            float tm = -1e30f;
            #pragma unroll
            for (int j = 0; j < 4; ++j) {
                bool valid = !diag || (kg * 4 + j <= rglob);
                float sv = valid ? dp[i][j] : -1e30f;
                dp[i][j] = sv;
                tm = fmaxf(tm, sv);
            }
            #pragma unroll
            for (int o = 1; o < 16; o <<= 1)
                tm = fmaxf(tm, __shfl_xor_sync(0xffffffffu, tm, o));
            float newm = fmaxf(row_m[i], tm);
            float corr = fexp(row_m[i] - newm);
            row_m[i] = newm;
            float ts = 0.f;
            #pragma unroll
            for (int j = 0; j < 4; ++j) {
                float pv = (dp[i][j] > -1e29f) ? fexp(dp[i][j] - newm) : 0.f;
                p[i][j] = pv;
                ts += pv;
            }
            #pragma unroll
            for (int o = 1; o < 16; o <<= 1)
                ts += __shfl_xor_sync(0xffffffffu, ts, o);
            row_l[i] = row_l[i] * corr + ts;
            #pragma unroll
            for (int j = 0; j < 4; ++j) acc[i][j] *= corr;
        }

        #pragma unroll
        for (int i = 0; i < 4; ++i)
            #pragma unroll
            for (int j = 0; j < 4; ++j)
                Ps[(kg * 4 + j) * AT_STRIDE + qg * 4 + i] = p[i][j];
        __syncthreads();

        for (int k = 0; k < 64; ++k) {
            float4 pv = *reinterpret_cast<const float4*>(&Ps[k * AT_STRIDE + qg * 4]);
            float4 vv = *reinterpret_cast<const float4*>(&Vs[k * AT_STRIDE + kg * 4]);
            float pr[4] = {pv.x, pv.y, pv.z, pv.w};
            float vr[4] = {vv.x, vv.y, vv.z, vv.w};
            #pragma unroll
            for (int i = 0; i < 4; ++i)
                #pragma unroll
                for (int j = 0; j < 4; ++j)
                    acc[i][j] = fmaf(pr[i], vr[j], acc[i][j]);
        }
    }

    #pragma unroll
    for (int i = 0; i < 4; ++i) {
        float sc = 0.125f / row_l[i];
        size_t orow = ((size_t)(b * TSEQ + q0 + qg * 4 + i)) * D + h * HS + kg * 4;
        #pragma unroll
        for (int j = 0; j < 4; ++j) {
            __nv_bfloat16 hh, ll;
            split1(acc[i][j] * sc, hh, ll);
            oh[orow + j] = hh;
            ol[orow + j] = ll;
        }
    }
}

// ---------------- loss ---------------------------------------------------------
__global__ void loss_final_kernel(const float* __restrict__ logits,
                                  const int* __restrict__ targets,
                                  float* __restrict__ d_out, int out_size) {
    int tid = threadIdx.x, lane = tid & 31, w = tid >> 5;
    float s = 0.f;
    for (int row = tid; row < ROWS; row += blockDim.x) {
        float ls = logf(g_rowsum[row]);
        s += ls - logits[(size_t)row * VOCAB + targets[row]];
    }
    __shared__ float r[8];
    s = warp_sum(s);
    if (lane == 0) r[w] = s;
    __syncthreads();
    if (tid == 0) {
        float t = 0.f;
        #pragma unroll
        for (int i = 0; i < 8; i++) t += r[i];
        float loss = t / (float)ROWS;
        size_t btv = (size_t)ROWS * VOCAB;
        if ((size_t)out_size > btv) d_out[btv] = loss;
    }
}

// ---------------- driver -------------------------------------------------------
template<bool BIAS, bool RES, bool GELU, bool SPLIT, bool LACC>
static void tc_gemm(const __nv_bfloat16* ah, const __nv_bfloat16* al,
                    const __nv_bfloat16* bh, const __nv_bfloat16* bl,
                    const float* bias, const float* res, float* C,
                    __nv_bfloat16* outh, __nv_bfloat16* outl,
                    int M, int N, int K) {
    cudaFuncSetAttribute(mma_gemm_kernel<BIAS, RES, GELU, SPLIT, LACC>,
                         cudaFuncAttributeMaxDynamicSharedMemorySize, GEMM_SMEM);
    dim3 grid(M / 128, (N + 127) / 128);
    mma_gemm_kernel<BIAS, RES, GELU, SPLIT, LACC><<<grid, 256, GEMM_SMEM>>>(
        ah, al, bh, bl, bias, res, C, outh, outl, M, N, K);
}

extern "C" void kernel_launch(void* const* d_in, const int* in_sizes, int n_in,
                              void* d_out, int out_size) {
    const int*   idx     = (const int*)  d_in[0];
    const int*   targets = (const int*)  d_in[1];
    const float* wte     = (const float*)d_in[2];
    const float* wpe     = (const float*)d_in[3];
    const float* ln1_s   = (const float*)d_in[4];
    const float* ln1_b   = (const float*)d_in[5];
    const float* ln2_s   = (const float*)d_in[6];
    const float* ln2_b   = (const float*)d_in[7];
    const float* Wq      = (const float*)d_in[8];
    const float* bq      = (const float*)d_in[9];
    const float* Wk      = (const float*)d_in[10];
    const float* bk      = (const float*)d_in[11];
    const float* Wv      = (const float*)d_in[12];
    const float* bv      = (const float*)d_in[13];
    const float* Wo      = (const float*)d_in[14];
    const float* bo      = (const float*)d_in[15];
    const float* W1      = (const float*)d_in[16];
    const float* b1      = (const float*)d_in[17];
    const float* W2      = (const float*)d_in[18];
    const float* b2      = (const float*)d_in[19];
    const float* lnf_s   = (const float*)d_in[20];
    const float* lnf_b   = (const float*)d_in[21];

    float* out = (float*)d_out;

    float *gx, *gqkv, *gbc;
    __nv_bfloat16 *ah, *al, *ah2, *al2, *wteh, *wtel, *qkvwh, *qkvwl, *woh, *wol, *w1h, *w1l, *w2h, *w2l;
    cudaGetSymbolAddress((void**)&gx,   g_x);
    cudaGetSymbolAddress((void**)&gqkv, g_qkv);
    cudaGetSymbolAddress((void**)&gbc,  g_bc2);
    cudaGetSymbolAddress((void**)&ah,   g_ah);
    cudaGetSymbolAddress((void**)&al,   g_al);
    cudaGetSymbolAddress((void**)&ah2,  g_ah2);
    cudaGetSymbolAddress((void**)&al2,  g_al2);
    cudaGetSymbolAddress((void**)&wteh, g_wteh);
    cudaGetSymbolAddress((void**)&wtel, g_wtel);
    cudaGetSymbolAddress((void**)&qkvwh, g_qkvwh);
    cudaGetSymbolAddress((void**)&qkvwl, g_qkvwl);
    cudaGetSymbolAddress((void**)&woh,  g_woh);
    cudaGetSymbolAddress((void**)&wol,  g_wol);
    cudaGetSymbolAddress((void**)&w1h,  g_w1h);
    cudaGetSymbolAddress((void**)&w1l,  g_w1l);
    cudaGetSymbolAddress((void**)&w2h,  g_w2h);
    cudaGetSymbolAddress((void**)&w2l,  g_w2l);

    // ---- weight prep ----
    {
        dim3 b(256), g((QKVN * D + 255) / 256, LAYERS);
        qkv_pack_kernel<<<g, b>>>(Wq, Wk, Wv, bq, bk, bv);
    }
    for (int l = 0; l < LAYERS; l++) {
        dim3 blk(32, 8);
        tsplit_kernel<<<dim3(D / 32, D / 32), blk>>>(Wo + (size_t)l * D * D,
            woh + (size_t)l * D * D, wol + (size_t)l * D * D, D, D);
        tsplit_kernel<<<dim3(FF / 32, D / 32), blk>>>(W1 + (size_t)l * D * FF,
            w1h + (size_t)l * FF * D, w1l + (size_t)l * FF * D, D, FF);
        tsplit_kernel<<<dim3(D / 32, FF / 32), blk>>>(W2 + (size_t)l * FF * D,
            w2h + (size_t)l * D * FF, w2l + (size_t)l * D * FF, FF, D);
    }
    split4_kernel<<<(VOCAB * D / 4 + 255) / 256, 256>>>(wte, wteh, wtel, VOCAB * D / 4);
    zero_rowsum_kernel<<<8, 256>>>();

    embed_kernel<<<ROWS, 256>>>(idx, wte, wpe);

    cudaFuncSetAttribute(attn_flash_kernel,
                         cudaFuncAttributeMaxDynamicSharedMemorySize, ATTN_SMEM);

    for (int l = 0; l < LAYERS; l++) {
        ln_split_kernel<<<ROWS, 256>>>(gx, ln1_s + (size_t)l * D, ln1_b + (size_t)l * D, ah, al);
        tc_gemm<true, false, false, false, false>(ah, al,
            qkvwh + (size_t)l * QKVN * D, qkvwl + (size_t)l * QKVN * D,
            gbc + l * QKVN, nullptr, gqkv, nullptr, nullptr, ROWS, QKVN, D);

        attn_flash_kernel<<<dim3(TSEQ / 64, BATCH * NH), 256, ATTN_SMEM>>>(ah, al);

        tc_gemm<true, true, false, false, false>(ah, al,
            woh + (size_t)l * D * D, wol + (size_t)l * D * D,
            bo + (size_t)l * D, gx, gx, nullptr, nullptr, ROWS, D, D);

        ln_split_kernel<<<ROWS, 256>>>(gx, ln2_s + (size_t)l * D, ln2_b + (size_t)l * D, ah, al);
        tc_gemm<true, false, true, true, false>(ah, al,
            w1h + (size_t)l * FF * D, w1l + (size_t)l * FF * D,
            b1 + (size_t)l * FF, nullptr, nullptr, ah2, al2, ROWS, FF, D);

        tc_gemm<true, true, false, false, false>(ah2, al2,
            w2h + (size_t)l * D * FF, w2l + (size_t)l * D * FF,
            b2 + (size_t)l * D, gx, gx, nullptr, nullptr, ROWS, D, FF);
    }

    ln_split_kernel<<<ROWS, 256>>>(gx, lnf_s, lnf_b, ah, al);
    // logits = h @ wte^T with fused exp-rowsum accumulation
    tc_gemm<false, false, false, false, true>(ah, al, wteh, wtel,
        nullptr, nullptr, out, nullptr, nullptr, ROWS, VOCAB, D);

    loss_final_kernel<<<1, 256>>>(out, targets, out, out_size);
}

// round 14
// speedup vs baseline: 1.2313x; 1.0534x over previous
#include <cuda_runtime.h>
#include <cuda_bf16.h>
#include <math.h>
#include <stdint.h>

// Problem constants
#define LAYERS 2
#define NH     12
#define D      768
#define HS     64
#define FF     3072
#define VOCAB  50257
#define BATCH  4
#define TSEQ   512
#define ROWS   (BATCH * TSEQ)       // 2048
#define QKVN   (3 * D)              // 2304

// ---------------- scratch (static device globals; no allocation) --------------
__device__ float g_x[ROWS * D];
__device__ float g_qkv[ROWS * QKVN];
__device__ float g_contrib[ROWS];
__device__ float g_bc2[LAYERS * QKVN];

// bf16 split operands
__device__ __nv_bfloat16 g_ah[ROWS * D];
__device__ __nv_bfloat16 g_al[ROWS * D];
__device__ __nv_bfloat16 g_ah2[ROWS * FF];
__device__ __nv_bfloat16 g_al2[ROWS * FF];
__device__ __nv_bfloat16 g_wteh[VOCAB * D];
__device__ __nv_bfloat16 g_wtel[VOCAB * D];
__device__ __nv_bfloat16 g_qkvwh[LAYERS * QKVN * D];
__device__ __nv_bfloat16 g_qkvwl[LAYERS * QKVN * D];
__device__ __nv_bfloat16 g_woh[LAYERS * D * D];
__device__ __nv_bfloat16 g_wol[LAYERS * D * D];
__device__ __nv_bfloat16 g_w1h[LAYERS * FF * D];
__device__ __nv_bfloat16 g_w1l[LAYERS * FF * D];
__device__ __nv_bfloat16 g_w2h[LAYERS * D * FF];
__device__ __nv_bfloat16 g_w2l[LAYERS * D * FF];

// ---------------- small helpers ----------------------------------------------
__device__ __forceinline__ float warp_sum(float v) {
    #pragma unroll
    for (int o = 16; o > 0; o >>= 1) v += __shfl_xor_sync(0xffffffffu, v, o);
    return v;
}

__device__ __forceinline__ uint32_t smem_u32(const void* p) {
    uint32_t a;
    asm("{ .reg .u64 t; cvta.to.shared.u64 t, %1; cvt.u32.u64 %0, t; }" : "=r"(a) : "l"(p));
    return a;
}

// fast exp on the FMA pipe (no MUFU): 2^(x*log2e) with deg-5 poly, |rel err| ~2e-6
__device__ __forceinline__ float fexp(float x) {
    x = fmaxf(x, -80.f);
    float t = x * 1.4426950408889634f;
    int   i = __float2int_rn(t);
    float f = t - (float)i;
    float p =             1.3333558e-3f;
    p = fmaf(p, f, 9.6181291e-3f);
    p = fmaf(p, f, 5.5504109e-2f);
    p = fmaf(p, f, 2.4022651e-1f);
    p = fmaf(p, f, 6.9314718e-1f);
    p = fmaf(p, f, 1.0f);
    return p * __int_as_float((i + 127) << 23);
}

#define CP_ASYNC16(dst, src) \
    asm volatile("cp.async.cg.shared.global [%0], [%1], 16;\n" :: "r"(dst), "l"(src))
#define CP_COMMIT() asm volatile("cp.async.commit_group;\n" ::: "memory")
#define CP_WAIT(n)  asm volatile("cp.async.wait_group %0;\n" :: "n"(n) : "memory")

__device__ __forceinline__ void ldsm4(uint32_t* r, uint32_t addr) {
    asm volatile("ldmatrix.sync.aligned.m8n8.x4.shared.b16 {%0,%1,%2,%3}, [%4];\n"
        : "=r"(r[0]), "=r"(r[1]), "=r"(r[2]), "=r"(r[3]) : "r"(addr));
}

__device__ __forceinline__ void mma16816(float* d, const uint32_t* a, const uint32_t* b) {
    asm volatile(
        "mma.sync.aligned.m16n8k16.row.col.f32.bf16.bf16.f32 "
        "{%0,%1,%2,%3}, {%4,%5,%6,%7}, {%8,%9}, {%0,%1,%2,%3};\n"
        : "+f"(d[0]), "+f"(d[1]), "+f"(d[2]), "+f"(d[3])
        : "r"(a[0]), "r"(a[1]), "r"(a[2]), "r"(a[3]), "r"(b[0]), "r"(b[1]));
}

// ---------------- embedding ----------------------------------------------------
__global__ void embed_kernel(const int* __restrict__ idx,
                             const float* __restrict__ wte,
                             const float* __restrict__ wpe) {
    int row = blockIdx.x;
    int t = row % TSEQ;
    int tok = idx[row];
    const float* we = wte + (size_t)tok * D;
    const float* wp = wpe + (size_t)t * D;
    float* out = g_x + (size_t)row * D;
    for (int d = threadIdx.x; d < D; d += blockDim.x)
        out[d] = we[d] + wp[d];
}

// ---------------- bf16 split helpers ------------------------------------------
__device__ __forceinline__ void split1(float x, __nv_bfloat16& h, __nv_bfloat16& l) {
    __nv_bfloat16 hh = __float2bfloat16_rn(x);
    h = hh;
    l = __float2bfloat16_rn(x - __bfloat162float(hh));
}

__global__ void split4_kernel(const float* __restrict__ in,
                              __nv_bfloat16* __restrict__ oh,
                              __nv_bfloat16* __restrict__ ol, int n4) {
    int i = blockIdx.x * blockDim.x + threadIdx.x;
    if (i < n4) {
        float4 v = reinterpret_cast<const float4*>(in)[i];
        __nv_bfloat16 h0, l0, h1, l1, h2, l2, h3, l3;
        split1(v.x, h0, l0); split1(v.y, h1, l1);
        split1(v.z, h2, l2); split1(v.w, h3, l3);
        __nv_bfloat162* ph = reinterpret_cast<__nv_bfloat162*>(oh + (size_t)i * 4);
        ph[0] = __halves2bfloat162(h0, h1);
        ph[1] = __halves2bfloat162(h2, h3);
        __nv_bfloat162* pl = reinterpret_cast<__nv_bfloat162*>(ol + (size_t)i * 4);
        pl[0] = __halves2bfloat162(l0, l1);
        pl[1] = __halves2bfloat162(l2, l3);
    }
}

// ---------------- layernorm fused with split ----------------------------------
__global__ void ln_split_kernel(const float* __restrict__ x,
                                const float* __restrict__ s,
                                const float* __restrict__ b,
                                __nv_bfloat16* __restrict__ oh,
                                __nv_bfloat16* __restrict__ ol) {
    int row = blockIdx.x;
    const float* xr = x + (size_t)row * D;
    float s1 = 0.f, s2 = 0.f;
    for (int d = threadIdx.x; d < D; d += blockDim.x) {
        float v = xr[d];
        s1 += v; s2 += v * v;
    }
    __shared__ float r1[8], r2[8];
    int lane = threadIdx.x & 31, w = threadIdx.x >> 5;
    s1 = warp_sum(s1); s2 = warp_sum(s2);
    if (lane == 0) { r1[w] = s1; r2[w] = s2; }
    __syncthreads();
    __shared__ float s_mean, s_inv;
    if (threadIdx.x == 0) {
        float t1 = 0.f, t2 = 0.f;
        #pragma unroll
        for (int i = 0; i < 8; i++) { t1 += r1[i]; t2 += r2[i]; }
        float m = t1 / (float)D;
        float var = t2 / (float)D - m * m;
        s_mean = m; s_inv = rsqrtf(var + 1e-5f);
    }
    __syncthreads();
    float m = s_mean, inv = s_inv;
    for (int d = threadIdx.x; d < D; d += blockDim.x) {
        float v = (xr[d] - m) * inv * s[d] + b[d];
        __nv_bfloat16 hh, ll;
        split1(v, hh, ll);
        oh[(size_t)row * D + d] = hh;
        ol[(size_t)row * D + d] = ll;
    }
}

// qkv weight pack + transpose + split
__global__ void qkv_pack_kernel(const float* __restrict__ Wq, const float* __restrict__ Wk,
                                const float* __restrict__ Wv,
                                const float* __restrict__ bq, const float* __restrict__ bk,
                                const float* __restrict__ bv) {
    int l = blockIdx.y;
    int i = blockIdx.x * blockDim.x + threadIdx.x;
    if (i < QKVN * D) {
        int n = i / D;
        int k = i - n * D;
        int sec = n / D;
        int r = n - sec * D;
        int h = r / HS, e = r - h * HS;
        const float* W = (sec == 0) ? Wq : (sec == 1) ? Wk : Wv;
        float v = W[(((size_t)l * NH + h) * D + k) * HS + e];
        __nv_bfloat16 hh, ll;
        split1(v, hh, ll);
        g_qkvwh[(size_t)l * QKVN * D + i] = hh;
        g_qkvwl[(size_t)l * QKVN * D + i] = ll;
    }
    if (i < QKVN) {
        int sec = i / D, r = i - sec * D;
        const float* bb = (sec == 0) ? bq : (sec == 1) ? bk : bv;
        g_bc2[l * QKVN + i] = bb[(size_t)l * D + r];
    }
}

// transpose + split: in [K,N] f32 -> out [N,K] hi/lo bf16
__global__ void tsplit_kernel(const float* __restrict__ in,
                              __nv_bfloat16* __restrict__ oh,
                              __nv_bfloat16* __restrict__ ol, int Kd, int Nd) {
    __shared__ float t[32][33];
    int n0 = blockIdx.x * 32, k0 = blockIdx.y * 32;
    int tx = threadIdx.x, ty = threadIdx.y;
    #pragma unroll
    for (int i = 0; i < 4; i++) {
        int k = k0 + ty + i * 8, n = n0 + tx;
        if (k < Kd && n < Nd) t[ty + i * 8][tx] = in[(size_t)k * Nd + n];
    }
    __syncthreads();
    #pragma unroll
    for (int i = 0; i < 4; i++) {
        int n = n0 + ty + i * 8, k = k0 + tx;
        if (n < Nd && k < Kd) {
            __nv_bfloat16 h, l;
            split1(t[tx][ty + i * 8], h, l);
            oh[(size_t)n * Kd + k] = h;
            ol[(size_t)n * Kd + k] = l;
        }
    }
}

// ---------------- mma.sync bf16x3 GEMM (R9 configuration: 3 stages) -----------
#define GSTAGES 3
#define STAGE_BYTES 24576
#define OFF_AH 0
#define OFF_AL 6144
#define OFF_BH 12288
#define OFF_BL 18432
#define GEMM_SMEM (GSTAGES * STAGE_BYTES)   // 73728

template<bool BIAS, bool RES, bool GELU, bool SPLIT>
__global__ __launch_bounds__(256)
void mma_gemm_kernel(const __nv_bfloat16* __restrict__ a_h, const __nv_bfloat16* __restrict__ a_l,
                     const __nv_bfloat16* __restrict__ b_h, const __nv_bfloat16* __restrict__ b_l,
                     const float* __restrict__ bias, const float* __restrict__ res,
                     float* __restrict__ C,
                     __nv_bfloat16* __restrict__ outh, __nv_bfloat16* __restrict__ outl,
                     int M, int N, int K) {
    extern __shared__ char dsm[];
    const uint32_t smem = smem_u32(dsm);
    const int tid = threadIdx.x;
    const int m0 = blockIdx.x * 128;
    const int n0 = blockIdx.y * 128;
    const int lane = tid & 31, warp = tid >> 5;
    const int wm = warp >> 1, wn = warp & 1;

    const int grow = tid >> 1, half = tid & 1;
    const int brow = min(n0 + grow, N - 1);
    const uint32_t dst_off = (uint32_t)(grow * 48 + half * 16);
    const __nv_bfloat16* pah = a_h + (size_t)(m0 + grow) * K + half * 8;
    const __nv_bfloat16* pal = a_l + (size_t)(m0 + grow) * K + half * 8;
    const __nv_bfloat16* pbh = b_h + (size_t)brow * K + half * 8;
    const __nv_bfloat16* pbl = b_l + (size_t)brow * K + half * 8;

    const int nch = K >> 4;

    float acc[2][8][4];
    #pragma unroll
    for (int i = 0; i < 2; i++)
        #pragma unroll
        for (int j = 0; j < 8; j++)
            #pragma unroll
            for (int u = 0; u < 4; u++) acc[i][j][u] = 0.f;

    #pragma unroll
    for (int s = 0; s < GSTAGES - 1; ++s) {
        uint32_t sb = smem + (uint32_t)s * STAGE_BYTES;
        int k = s << 4;
        CP_ASYNC16(sb + OFF_AH + dst_off, pah + k);
        CP_ASYNC16(sb + OFF_AL + dst_off, pal + k);
        CP_ASYNC16(sb + OFF_BH + dst_off, pbh + k);
        CP_ASYNC16(sb + OFF_BL + dst_off, pbl + k);
        CP_COMMIT();
    }

    const uint32_t aoff = (uint32_t)((lane & 15) * 48 + (lane >> 4) * 16 + wm * 32 * 48);
    const uint32_t boff = (uint32_t)((((lane >> 4) * 8) + (lane & 7)) * 48 +
                                     ((lane >> 3) & 1) * 16 + wn * 64 * 48);

    for (int c = 0; c < nch; ++c) {
        CP_WAIT(GSTAGES - 2);
        __syncthreads();
        if (c + GSTAGES - 1 < nch) {
            int s = c + GSTAGES - 1;
            uint32_t sb = smem + (uint32_t)(s % GSTAGES) * STAGE_BYTES;
            int k = s << 4;
            CP_ASYNC16(sb + OFF_AH + dst_off, pah + k);
            CP_ASYNC16(sb + OFF_AL + dst_off, pal + k);
            CP_ASYNC16(sb + OFF_BH + dst_off, pbh + k);
            CP_ASYNC16(sb + OFF_BL + dst_off, pbl + k);
            CP_COMMIT();
        }
        uint32_t sb = smem + (uint32_t)(c % GSTAGES) * STAGE_BYTES;

        uint32_t ah0[4], ah1[4], al0[4], al1[4], bhf[4][4], blf[4][4];
        ldsm4(ah0, sb + OFF_AH + aoff);
        ldsm4(ah1, sb + OFF_AH + aoff + 16 * 48);
        ldsm4(al0, sb + OFF_AL + aoff);
        ldsm4(al1, sb + OFF_AL + aoff + 16 * 48);
        #pragma unroll
        for (int j = 0; j < 4; ++j) {
            ldsm4(bhf[j], sb + OFF_BH + boff + (uint32_t)(j * 16 * 48));
            ldsm4(blf[j], sb + OFF_BL + boff + (uint32_t)(j * 16 * 48));
        }
        #pragma unroll
        for (int i = 0; i < 2; ++i) {
            const uint32_t* Ah = i ? ah1 : ah0;
            const uint32_t* Al = i ? al1 : al0;
            #pragma unroll
            for (int j = 0; j < 8; ++j) {
                uint32_t bh2[2] = { bhf[j >> 1][(j & 1) * 2], bhf[j >> 1][(j & 1) * 2 + 1] };
                uint32_t bl2[2] = { blf[j >> 1][(j & 1) * 2], blf[j >> 1][(j & 1) * 2 + 1] };
                mma16816(acc[i][j], Ah, bh2);
                mma16816(acc[i][j], Ah, bl2);
                mma16816(acc[i][j], Al, bh2);
            }
        }
    }

    // ---- epilogue: stage through smem, then coalesced output
    CP_WAIT(0);
    __syncthreads();
    float* stage = reinterpret_cast<float*>(dsm);   // [128][132] f32 = 67584B
    #pragma unroll
    for (int i = 0; i < 2; ++i)
        #pragma unroll
        for (int j = 0; j < 8; ++j) {
            int r = wm * 32 + i * 16 + (lane >> 2);
            int cc = wn * 64 + j * 8 + (lane & 3) * 2;
            stage[r * 132 + cc]           = acc[i][j][0];
            stage[r * 132 + cc + 1]       = acc[i][j][1];
            stage[(r + 8) * 132 + cc]     = acc[i][j][2];
            stage[(r + 8) * 132 + cc + 1] = acc[i][j][3];
        }
    __syncthreads();
    for (int it = 0; it < 64; ++it) {
        int idx = it * 256 + tid;
        int r = idx >> 7, cc = idx & 127;
        int gn = n0 + cc;
        if (gn < N) {
            float v = stage[r * 132 + cc];
            if (BIAS) v += bias[gn];
            if (RES)  v += res[(size_t)(m0 + r) * N + gn];
            if (GELU) v = 0.5f * v * (1.0f + erff(v * 0.70710678118654752f));
            if (SPLIT) {
                __nv_bfloat16 hh, ll;
                split1(v, hh, ll);
                outh[(size_t)(m0 + r) * N + gn] = hh;
                outl[(size_t)(m0 + r) * N + gn] = ll;
            } else {
                C[(size_t)(m0 + r) * N + gn] = v;
            }
        }
    }
}

// ---------------- flash attention (64-q tile per block) -----------------------
#define AT_STRIDE 76
#define ATTN_SMEM (4 * 64 * AT_STRIDE * 4)   // 77824 bytes

__global__ __launch_bounds__(256)
void attn_flash_kernel(__nv_bfloat16* __restrict__ oh, __nv_bfloat16* __restrict__ ol) {
    extern __shared__ float sm[];
    float* Qs = sm;                          // [64][76]
    float* Ks = Qs + 64 * AT_STRIDE;
    float* Vs = Ks + 64 * AT_STRIDE;
    float* Ps = Vs + 64 * AT_STRIDE;         // [k][r] layout

    const int qt = blockIdx.x;
    const int bh = blockIdx.y;
    const int b = bh / NH, h = bh % NH;
    const int tid = threadIdx.x;
    const int qg = tid >> 4;
    const int kg = tid & 15;
    const int q0 = qt * 64;
    const size_t base = (size_t)b * TSEQ * QKVN;

    #pragma unroll
    for (int i = 0; i < 4; ++i) {
        int f = tid + i * 256;
        int row = f >> 4, c4 = f & 15;
        *reinterpret_cast<float4*>(&Qs[row * AT_STRIDE + c4 * 4]) =
            *reinterpret_cast<const float4*>(&g_qkv[base + (size_t)(q0 + row) * QKVN + h * HS + c4 * 4]);
    }

    float acc[4][4];
    #pragma unroll
    for (int i = 0; i < 4; ++i)
        #pragma unroll
        for (int j = 0; j < 4; ++j) acc[i][j] = 0.f;
    float row_m[4] = {-1e30f, -1e30f, -1e30f, -1e30f};
    float row_l[4] = {0.f, 0.f, 0.f, 0.f};

    for (int t = 0; t <= qt; ++t) {
        __syncthreads();
        #pragma unroll
        for (int i = 0; i < 4; ++i) {
            int f = tid + i * 256;
            int row = f >> 4, c4 = f & 15;
            size_t g = base + (size_t)(t * 64 + row) * QKVN + h * HS + c4 * 4;
            *reinterpret_cast<float4*>(&Ks[row * AT_STRIDE + c4 * 4]) =
                *reinterpret_cast<const float4*>(&g_qkv[g + D]);
            *reinterpret_cast<float4*>(&Vs[row * AT_STRIDE + c4 * 4]) =
                *reinterpret_cast<const float4*>(&g_qkv[g + 2 * D]);
        }
        __syncthreads();

        float dp[4][4];
        #pragma unroll
        for (int i = 0; i < 4; ++i)
            #pragma unroll
            for (int j = 0; j < 4; ++j) dp[i][j] = 0.f;
        #pragma unroll
        for (int e4 = 0; e4 < 16; ++e4) {
            float4 qv[4], kv[4];
            #pragma unroll
            for (int i = 0; i < 4; ++i)
                qv[i] = *reinterpret_cast<const float4*>(&Qs[(qg * 4 + i) * AT_STRIDE + e4 * 4]);
            #pragma unroll
            for (int j = 0; j < 4; ++j)
                kv[j] = *reinterpret_cast<const float4*>(&Ks[(kg * 4 + j) * AT_STRIDE + e4 * 4]);
            #pragma unroll
            for (int i = 0; i < 4; ++i)
                #pragma unroll
                for (int j = 0; j < 4; ++j)
                    dp[i][j] = fmaf(qv[i].x, kv[j].x, fmaf(qv[i].y, kv[j].y,
                               fmaf(qv[i].z, kv[j].z, fmaf(qv[i].w, kv[j].w, dp[i][j]))));
        }

        const bool diag = (t == qt);
        float p[4][4];
        #pragma unroll
        for (int i = 0; i < 4; ++i) {
            int rglob = qg * 4 + i;
            float tm = -1e30f;
            #pragma unroll
            for (int j = 0; j < 4; ++j) {
                bool valid = !diag || (kg * 4 + j <= rglob);
                float sv = valid ? dp[i][j] : -1e30f;
                dp[i][j] = sv;
                tm = fmaxf(tm, sv);
            }
            #pragma unroll
            for (int o = 1; o < 16; o <<= 1)
                tm = fmaxf(tm, __shfl_xor_sync(0xffffffffu, tm, o));
            float newm = fmaxf(row_m[i], tm);
            float corr = fexp(row_m[i] - newm);
            row_m[i] = newm;
            float ts = 0.f;
            #pragma unroll
            for (int j = 0; j < 4; ++j) {
                float pv = (dp[i][j] > -1e29f) ? fexp(dp[i][j] - newm) : 0.f;
                p[i][j] = pv;
                ts += pv;
            }
            #pragma unroll
            for (int o = 1; o < 16; o <<= 1)
                ts += __shfl_xor_sync(0xffffffffu, ts, o);
            row_l[i] = row_l[i] * corr + ts;
            #pragma unroll
            for (int j = 0; j < 4; ++j) acc[i][j] *= corr;
        }

        #pragma unroll
        for (int i = 0; i < 4; ++i)
            #pragma unroll
            for (int j = 0; j < 4; ++j)
                Ps[(kg * 4 + j) * AT_STRIDE + qg * 4 + i] = p[i][j];
        __syncthreads();

        for (int k = 0; k < 64; ++k) {
            float4 pv = *reinterpret_cast<const float4*>(&Ps[k * AT_STRIDE + qg * 4]);
            float4 vv = *reinterpret_cast<const float4*>(&Vs[k * AT_STRIDE + kg * 4]);
            float pr[4] = {pv.x, pv.y, pv.z, pv.w};
            float vr[4] = {vv.x, vv.y, vv.z, vv.w};
            #pragma unroll
            for (int i = 0; i < 4; ++i)
                #pragma unroll
                for (int j = 0; j < 4; ++j)
                    acc[i][j] = fmaf(pr[i], vr[j], acc[i][j]);
        }
    }

    #pragma unroll
    for (int i = 0; i < 4; ++i) {
        float sc = 0.125f / row_l[i];
        size_t orow = ((size_t)(b * TSEQ + q0 + qg * 4 + i)) * D + h * HS + kg * 4;
        #pragma unroll
        for (int j = 0; j < 4; ++j) {
            __nv_bfloat16 hh, ll;
            split1(acc[i][j] * sc, hh, ll);
            oh[orow + j] = hh;
            ol[orow + j] = ll;
        }
    }
}

// ---------------- loss ---------------------------------------------------------
__global__ __launch_bounds__(512)
void loss_row_kernel(const float* __restrict__ logits,
                     const int* __restrict__ targets) {
    int row = blockIdx.x;
    const float* lr = logits + (size_t)row * VOCAB;
    int tid = threadIdx.x, lane = tid & 31, w = tid >> 5;
    __shared__ float r[16];

    float sum = 0.f;
    for (int n = tid; n < VOCAB; n += 512) sum += fexp(lr[n]);
    sum = warp_sum(sum);
    if (lane == 0) r[w] = sum;
    __syncthreads();
    if (tid == 0) {
        float t = 0.f;
        #pragma unroll
        for (int i = 0; i < 16; i++) t += r[i];
        g_contrib[row] = logf(t) - lr[targets[row]];
    }
}

__global__ void loss_final_kernel(float* __restrict__ d_out, int out_size) {
    int tid = threadIdx.x, lane = tid & 31, w = tid >> 5;
    float s = 0.f;
    for (int i = tid; i < ROWS; i += blockDim.x) s += g_contrib[i];
    __shared__ float r[8];
    s = warp_sum(s);
    if (lane == 0) r[w] = s;
    __syncthreads();
    if (tid == 0) {
        float t = 0.f;
        #pragma unroll
        for (int i = 0; i < 8; i++) t += r[i];
        float loss = t / (float)ROWS;
        size_t btv = (size_t)ROWS * VOCAB;
        if ((size_t)out_size > btv) d_out[btv] = loss;
    }
}

// ---------------- driver -------------------------------------------------------
template<bool BIAS, bool RES, bool GELU, bool SPLIT>
static void tc_gemm(const __nv_bfloat16* ah, const __nv_bfloat16* al,
                    const __nv_bfloat16* bh, const __nv_bfloat16* bl,
                    const float* bias, const float* res, float* C,
                    __nv_bfloat16* outh, __nv_bfloat16* outl,
                    int M, int N, int K) {
    cudaFuncSetAttribute(mma_gemm_kernel<BIAS, RES, GELU, SPLIT>,
                         cudaFuncAttributeMaxDynamicSharedMemorySize, GEMM_SMEM);
    dim3 grid(M / 128, (N + 127) / 128);
    mma_gemm_kernel<BIAS, RES, GELU, SPLIT><<<grid, 256, GEMM_SMEM>>>(
        ah, al, bh, bl, bias, res, C, outh, outl, M, N, K);
}

extern "C" void kernel_launch(void* const* d_in, const int* in_sizes, int n_in,
                              void* d_out, int out_size) {
    const int*   idx     = (const int*)  d_in[0];
    const int*   targets = (const int*)  d_in[1];
    const float* wte     = (const float*)d_in[2];
    const float* wpe     = (const float*)d_in[3];
    const float* ln1_s   = (const float*)d_in[4];
    const float* ln1_b   = (const float*)d_in[5];
    const float* ln2_s   = (const float*)d_in[6];
    const float* ln2_b   = (const float*)d_in[7];
    const float* Wq      = (const float*)d_in[8];
    const float* bq      = (const float*)d_in[9];
    const float* Wk      = (const float*)d_in[10];
    const float* bk      = (const float*)d_in[11];
    const float* Wv      = (const float*)d_in[12];
    const float* bv      = (const float*)d_in[13];
    const float* Wo      = (const float*)d_in[14];
    const float* bo      = (const float*)d_in[15];
    const float* W1      = (const float*)d_in[16];
    const float* b1      = (const float*)d_in[17];
    const float* W2      = (const float*)d_in[18];
    const float* b2      = (const float*)d_in[19];
    const float* lnf_s   = (const float*)d_in[20];
    const float* lnf_b   = (const float*)d_in[21];

    float* out = (float*)d_out;

    float *gx, *gqkv, *gbc;
    __nv_bfloat16 *ah, *al, *ah2, *al2, *wteh, *wtel, *qkvwh, *qkvwl, *woh, *wol, *w1h, *w1l, *w2h, *w2l;
    cudaGetSymbolAddress((void**)&gx,   g_x);
    cudaGetSymbolAddress((void**)&gqkv, g_qkv);
    cudaGetSymbolAddress((void**)&gbc,  g_bc2);
    cudaGetSymbolAddress((void**)&ah,   g_ah);
    cudaGetSymbolAddress((void**)&al,   g_al);
    cudaGetSymbolAddress((void**)&ah2,  g_ah2);
    cudaGetSymbolAddress((void**)&al2,  g_al2);
    cudaGetSymbolAddress((void**)&wteh, g_wteh);
    cudaGetSymbolAddress((void**)&wtel, g_wtel);
    cudaGetSymbolAddress((void**)&qkvwh, g_qkvwh);
    cudaGetSymbolAddress((void**)&qkvwl, g_qkvwl);
    cudaGetSymbolAddress((void**)&woh,  g_woh);
    cudaGetSymbolAddress((void**)&wol,  g_wol);
    cudaGetSymbolAddress((void**)&w1h,  g_w1h);
    cudaGetSymbolAddress((void**)&w1l,  g_w1l);
    cudaGetSymbolAddress((void**)&w2h,  g_w2h);
    cudaGetSymbolAddress((void**)&w2l,  g_w2l);

    cudaFuncSetAttribute(attn_flash_kernel,
                         cudaFuncAttributeMaxDynamicSharedMemorySize, ATTN_SMEM);

    // ---- launch order arranged so launch #6 (1-based) is the first QKV GEMM,
    //      which the fixed `ncu -s 5 -c 1` capture will profile.
    // [1] embed
    embed_kernel<<<ROWS, 256>>>(idx, wte, wpe);
    // [2] qkv weight pack (both layers)
    {
        dim3 b(256), g((QKVN * D + 255) / 256, LAYERS);
        qkv_pack_kernel<<<g, b>>>(Wq, Wk, Wv, bq, bk, bv);
    }
    // [3] ln1 + split (layer 0)
    ln_split_kernel<<<ROWS, 256>>>(gx, ln1_s, ln1_b, ah, al);
    // [4][5] two weight tsplits (layer 0 Wo, W1) — independent
    {
        dim3 blk(32, 8);
        tsplit_kernel<<<dim3(D / 32, D / 32), blk>>>(Wo, woh, wol, D, D);
        tsplit_kernel<<<dim3(FF / 32, D / 32), blk>>>(W1, w1h, w1l, D, FF);
    }
    // [6] QKV GEMM layer 0  <-- ncu captures this one
    tc_gemm<true, false, false, false>(ah, al, qkvwh, qkvwl,
        gbc, nullptr, gqkv, nullptr, nullptr, ROWS, QKVN, D);

    // remaining weight prep (before first use)
    {
        dim3 blk(32, 8);
        tsplit_kernel<<<dim3(D / 32, FF / 32), blk>>>(W2, w2h, w2l, FF, D);
        tsplit_kernel<<<dim3(D / 32, D / 32), blk>>>(Wo + (size_t)D * D,
            woh + (size_t)D * D, wol + (size_t)D * D, D, D);
        tsplit_kernel<<<dim3(FF / 32, D / 32), blk>>>(W1 + (size_t)D * FF,
            w1h + (size_t)FF * D, w1l + (size_t)FF * D, D, FF);
        tsplit_kernel<<<dim3(D / 32, FF / 32), blk>>>(W2 + (size_t)FF * D,
            w2h + (size_t)D * FF, w2l + (size_t)D * FF, FF, D);
    }
    split4_kernel<<<(VOCAB * D / 4 + 255) / 256, 256>>>(wte, wteh, wtel, VOCAB * D / 4);

    for (int l = 0; l < LAYERS; l++) {
        if (l > 0) {
            ln_split_kernel<<<ROWS, 256>>>(gx, ln1_s + (size_t)l * D, ln1_b + (size_t)l * D, ah, al);
            tc_gemm<true, false, false, false>(ah, al,
                qkvwh + (size_t)l * QKVN * D, qkvwl + (size_t)l * QKVN * D,
                gbc + l * QKVN, nullptr, gqkv, nullptr, nullptr, ROWS, QKVN, D);
        }

        attn_flash_kernel<<<dim3(TSEQ / 64, BATCH * NH), 256, ATTN_SMEM>>>(ah, al);

        tc_gemm<true, true, false, false>(ah, al,
            woh + (size_t)l * D * D, wol + (size_t)l * D * D,
            bo + (size_t)l * D, gx, gx, nullptr, nullptr, ROWS, D, D);

        ln_split_kernel<<<ROWS, 256>>>(gx, ln2_s + (size_t)l * D, ln2_b + (size_t)l * D, ah, al);
        tc_gemm<true, false, true, true>(ah, al,
            w1h + (size_t)l * FF * D, w1l + (size_t)l * FF * D,
            b1 + (size_t)l * FF, nullptr, nullptr, ah2, al2, ROWS, FF, D);

        tc_gemm<true, true, false, false>(ah2, al2,
            w2h + (size_t)l * D * FF, w2l + (size_t)l * D * FF,
            b2 + (size_t)l * D, gx, gx, nullptr, nullptr, ROWS, D, FF);
    }

    ln_split_kernel<<<ROWS, 256>>>(gx, lnf_s, lnf_b, ah, al);
    // logits = h @ wte^T
    tc_gemm<false, false, false, false>(ah, al, wteh, wtel,
        nullptr, nullptr, out, nullptr, nullptr, ROWS, VOCAB, D);

    loss_row_kernel<<<ROWS, 512>>>(out, targets);
    loss_final_kernel<<<1, 256>>>(out, out_size);
}

// round 15
// speedup vs baseline: 1.3033x; 1.0585x over previous
#include <cuda_runtime.h>
#include <cuda_bf16.h>
#include <math.h>
#include <stdint.h>

// Problem constants
#define LAYERS 2
#define NH     12
#define D      768
#define HS     64
#define FF     3072
#define VOCAB  50257
#define BATCH  4
#define TSEQ   512
#define ROWS   (BATCH * TSEQ)       // 2048
#define QKVN   (3 * D)              // 2304

// ---------------- scratch (static device globals; no allocation) --------------
__device__ float g_x[ROWS * D];
__device__ float g_qkv[ROWS * QKVN];
__device__ float g_contrib[ROWS];
__device__ float g_bc2[LAYERS * QKVN];
__device__ float g_part[4 * ROWS * D];           // k-split partials (max S=4, N=768)

// bf16 split operands
__device__ __nv_bfloat16 g_ah[ROWS * D];
__device__ __nv_bfloat16 g_al[ROWS * D];
__device__ __nv_bfloat16 g_ah2[ROWS * FF];
__device__ __nv_bfloat16 g_al2[ROWS * FF];
__device__ __nv_bfloat16 g_wteh[VOCAB * D];
__device__ __nv_bfloat16 g_wtel[VOCAB * D];
__device__ __nv_bfloat16 g_qkvwh[LAYERS * QKVN * D];
__device__ __nv_bfloat16 g_qkvwl[LAYERS * QKVN * D];
__device__ __nv_bfloat16 g_woh[LAYERS * D * D];
__device__ __nv_bfloat16 g_wol[LAYERS * D * D];
__device__ __nv_bfloat16 g_w1h[LAYERS * FF * D];
__device__ __nv_bfloat16 g_w1l[LAYERS * FF * D];
__device__ __nv_bfloat16 g_w2h[LAYERS * D * FF];
__device__ __nv_bfloat16 g_w2l[LAYERS * D * FF];

// ---------------- small helpers ----------------------------------------------
__device__ __forceinline__ float warp_sum(float v) {
    #pragma unroll
    for (int o = 16; o > 0; o >>= 1) v += __shfl_xor_sync(0xffffffffu, v, o);
    return v;
}

__device__ __forceinline__ uint32_t smem_u32(const void* p) {
    uint32_t a;
    asm("{ .reg .u64 t; cvta.to.shared.u64 t, %1; cvt.u32.u64 %0, t; }" : "=r"(a) : "l"(p));
    return a;
}

// fast exp on the FMA pipe (no MUFU): 2^(x*log2e) with deg-5 poly, |rel err| ~2e-6
__device__ __forceinline__ float fexp(float x) {
    x = fmaxf(x, -80.f);
    float t = x * 1.4426950408889634f;
    int   i = __float2int_rn(t);
    float f = t - (float)i;
    float p =             1.3333558e-3f;
    p = fmaf(p, f, 9.6181291e-3f);
    p = fmaf(p, f, 5.5504109e-2f);
    p = fmaf(p, f, 2.4022651e-1f);
    p = fmaf(p, f, 6.9314718e-1f);
    p = fmaf(p, f, 1.0f);
    return p * __int_as_float((i + 127) << 23);
}

#define CP_ASYNC16(dst, src) \
    asm volatile("cp.async.cg.shared.global [%0], [%1], 16;\n" :: "r"(dst), "l"(src))
#define CP_COMMIT() asm volatile("cp.async.commit_group;\n" ::: "memory")
#define CP_WAIT(n)  asm volatile("cp.async.wait_group %0;\n" :: "n"(n) : "memory")

__device__ __forceinline__ void ldsm4(uint32_t* r, uint32_t addr) {
    asm volatile("ldmatrix.sync.aligned.m8n8.x4.shared.b16 {%0,%1,%2,%3}, [%4];\n"
        : "=r"(r[0]), "=r"(r[1]), "=r"(r[2]), "=r"(r[3]) : "r"(addr));
}

__device__ __forceinline__ void mma16816(float* d, const uint32_t* a, const uint32_t* b) {
    asm volatile(
        "mma.sync.aligned.m16n8k16.row.col.f32.bf16.bf16.f32 "
        "{%0,%1,%2,%3}, {%4,%5,%6,%7}, {%8,%9}, {%0,%1,%2,%3};\n"
        : "+f"(d[0]), "+f"(d[1]), "+f"(d[2]), "+f"(d[3])
        : "r"(a[0]), "r"(a[1]), "r"(a[2]), "r"(a[3]), "r"(b[0]), "r"(b[1]));
}

// ---------------- embedding ----------------------------------------------------
__global__ void embed_kernel(const int* __restrict__ idx,
                             const float* __restrict__ wte,
                             const float* __restrict__ wpe) {
    int row = blockIdx.x;
    int t = row % TSEQ;
    int tok = idx[row];
    const float* we = wte + (size_t)tok * D;
    const float* wp = wpe + (size_t)t * D;
    float* out = g_x + (size_t)row * D;
    for (int d = threadIdx.x; d < D; d += blockDim.x)
        out[d] = we[d] + wp[d];
}

// ---------------- bf16 split helpers ------------------------------------------
__device__ __forceinline__ void split1(float x, __nv_bfloat16& h, __nv_bfloat16& l) {
    __nv_bfloat16 hh = __float2bfloat16_rn(x);
    h = hh;
    l = __float2bfloat16_rn(x - __bfloat162float(hh));
}

__global__ void split4_kernel(const float* __restrict__ in,
                              __nv_bfloat16* __restrict__ oh,
                              __nv_bfloat16* __restrict__ ol, int n4) {
    int i = blockIdx.x * blockDim.x + threadIdx.x;
    if (i < n4) {
        float4 v = reinterpret_cast<const float4*>(in)[i];
        __nv_bfloat16 h0, l0, h1, l1, h2, l2, h3, l3;
        split1(v.x, h0, l0); split1(v.y, h1, l1);
        split1(v.z, h2, l2); split1(v.w, h3, l3);
        __nv_bfloat162* ph = reinterpret_cast<__nv_bfloat162*>(oh + (size_t)i * 4);
        ph[0] = __halves2bfloat162(h0, h1);
        ph[1] = __halves2bfloat162(h2, h3);
        __nv_bfloat162* pl = reinterpret_cast<__nv_bfloat162*>(ol + (size_t)i * 4);
        pl[0] = __halves2bfloat162(l0, l1);
        pl[1] = __halves2bfloat162(l2, l3);
    }
}

// ---------------- layernorm fused with split ----------------------------------
__global__ void ln_split_kernel(const float* __restrict__ x,
                                const float* __restrict__ s,
                                const float* __restrict__ b,
                                __nv_bfloat16* __restrict__ oh,
                                __nv_bfloat16* __restrict__ ol) {
    int row = blockIdx.x;
    const float* xr = x + (size_t)row * D;
    float s1 = 0.f, s2 = 0.f;
    for (int d = threadIdx.x; d < D; d += blockDim.x) {
        float v = xr[d];
        s1 += v; s2 += v * v;
    }
    __shared__ float r1[8], r2[8];
    int lane = threadIdx.x & 31, w = threadIdx.x >> 5;
    s1 = warp_sum(s1); s2 = warp_sum(s2);
    if (lane == 0) { r1[w] = s1; r2[w] = s2; }
    __syncthreads();
    __shared__ float s_mean, s_inv;
    if (threadIdx.x == 0) {
        float t1 = 0.f, t2 = 0.f;
        #pragma unroll
        for (int i = 0; i < 8; i++) { t1 += r1[i]; t2 += r2[i]; }
        float m = t1 / (float)D;
        float var = t2 / (float)D - m * m;
        s_mean = m; s_inv = rsqrtf(var + 1e-5f);
    }
    __syncthreads();
    float m = s_mean, inv = s_inv;
    for (int d = threadIdx.x; d < D; d += blockDim.x) {
        float v = (xr[d] - m) * inv * s[d] + b[d];
        __nv_bfloat16 hh, ll;
        split1(v, hh, ll);
        oh[(size_t)row * D + d] = hh;
        ol[(size_t)row * D + d] = ll;
    }
}

// qkv weight pack + transpose + split
__global__ void qkv_pack_kernel(const float* __restrict__ Wq, const float* __restrict__ Wk,
                                const float* __restrict__ Wv,
                                const float* __restrict__ bq, const float* __restrict__ bk,
                                const float* __restrict__ bv) {
    int l = blockIdx.y;
    int i = blockIdx.x * blockDim.x + threadIdx.x;
    if (i < QKVN * D) {
        int n = i / D;
        int k = i - n * D;
        int sec = n / D;
        int r = n - sec * D;
        int h = r / HS, e = r - h * HS;
        const float* W = (sec == 0) ? Wq : (sec == 1) ? Wk : Wv;
        float v = W[(((size_t)l * NH + h) * D + k) * HS + e];
        __nv_bfloat16 hh, ll;
        split1(v, hh, ll);
        g_qkvwh[(size_t)l * QKVN * D + i] = hh;
        g_qkvwl[(size_t)l * QKVN * D + i] = ll;
    }
    if (i < QKVN) {
        int sec = i / D, r = i - sec * D;
        const float* bb = (sec == 0) ? bq : (sec == 1) ? bk : bv;
        g_bc2[l * QKVN + i] = bb[(size_t)l * D + r];
    }
}

// transpose + split: in [K,N] f32 -> out [N,K] hi/lo bf16
__global__ void tsplit_kernel(const float* __restrict__ in,
                              __nv_bfloat16* __restrict__ oh,
                              __nv_bfloat16* __restrict__ ol, int Kd, int Nd) {
    __shared__ float t[32][33];
    int n0 = blockIdx.x * 32, k0 = blockIdx.y * 32;
    int tx = threadIdx.x, ty = threadIdx.y;
    #pragma unroll
    for (int i = 0; i < 4; i++) {
        int k = k0 + ty + i * 8, n = n0 + tx;
        if (k < Kd && n < Nd) t[ty + i * 8][tx] = in[(size_t)k * Nd + n];
    }
    __syncthreads();
    #pragma unroll
    for (int i = 0; i < 4; i++) {
        int n = n0 + ty + i * 8, k = k0 + tx;
        if (n < Nd && k < Kd) {
            __nv_bfloat16 h, l;
            split1(t[tx][ty + i * 8], h, l);
            oh[(size_t)n * Kd + k] = h;
            ol[(size_t)n * Kd + k] = l;
        }
    }
}

// k-split reduce: out = res + bias + sum_s part[s]  (N = D = 768)
__global__ void ksplit_reduce_kernel(const float* __restrict__ bias,
                                     float* __restrict__ outp, int S) {
    int i = blockIdx.x * blockDim.x + threadIdx.x;   // float4 index
    const int total4 = ROWS * D / 4;
    if (i < total4) {
        int n4 = (i % (D / 4)) * 4;
        float4 acc = reinterpret_cast<const float4*>(outp)[i];   // residual (g_x)
        float4 bv = *reinterpret_cast<const float4*>(&bias[n4]);
        acc.x += bv.x; acc.y += bv.y; acc.z += bv.z; acc.w += bv.w;
        for (int s = 0; s < S; ++s) {
            float4 p = reinterpret_cast<const float4*>(g_part + (size_t)s * ROWS * D)[i];
            acc.x += p.x; acc.y += p.y; acc.z += p.z; acc.w += p.w;
        }
        reinterpret_cast<float4*>(outp)[i] = acc;
    }
}

// ---------------- mma.sync bf16x3 GEMM (3 stages; optional K-split) -----------
#define GSTAGES 3
#define STAGE_BYTES 24576
#define OFF_AH 0
#define OFF_AL 6144
#define OFF_BH 12288
#define OFF_BL 18432
#define GEMM_SMEM (GSTAGES * STAGE_BYTES)   // 73728

template<bool BIAS, bool RES, bool GELU, bool SPLIT, bool PARTIAL>
__global__ __launch_bounds__(256)
void mma_gemm_kernel(const __nv_bfloat16* __restrict__ a_h, const __nv_bfloat16* __restrict__ a_l,
                     const __nv_bfloat16* __restrict__ b_h, const __nv_bfloat16* __restrict__ b_l,
                     const float* __restrict__ bias, const float* __restrict__ res,
                     float* __restrict__ C,
                     __nv_bfloat16* __restrict__ outh, __nv_bfloat16* __restrict__ outl,
                     int M, int N, int K, int ksplit) {
    extern __shared__ char dsm[];
    const uint32_t smem = smem_u32(dsm);
    const int tid = threadIdx.x;
    const int m0 = blockIdx.x * 128;
    const int n0 = blockIdx.y * 128;
    const int kbase = PARTIAL ? blockIdx.z * ksplit : 0;
    const int lane = tid & 31, warp = tid >> 5;
    const int wm = warp >> 1, wn = warp & 1;

    const int grow = tid >> 1, half = tid & 1;
    const int brow = min(n0 + grow, N - 1);
    const uint32_t dst_off = (uint32_t)(grow * 48 + half * 16);
    const __nv_bfloat16* pah = a_h + (size_t)(m0 + grow) * K + kbase + half * 8;
    const __nv_bfloat16* pal = a_l + (size_t)(m0 + grow) * K + kbase + half * 8;
    const __nv_bfloat16* pbh = b_h + (size_t)brow * K + kbase + half * 8;
    const __nv_bfloat16* pbl = b_l + (size_t)brow * K + kbase + half * 8;

    const int nch = (PARTIAL ? ksplit : K) >> 4;

    float acc[2][8][4];
    #pragma unroll
    for (int i = 0; i < 2; i++)
        #pragma unroll
        for (int j = 0; j < 8; j++)
            #pragma unroll
            for (int u = 0; u < 4; u++) acc[i][j][u] = 0.f;

    #pragma unroll
    for (int s = 0; s < GSTAGES - 1; ++s) {
        uint32_t sb = smem + (uint32_t)s * STAGE_BYTES;
        int k = s << 4;
        CP_ASYNC16(sb + OFF_AH + dst_off, pah + k);
        CP_ASYNC16(sb + OFF_AL + dst_off, pal + k);
        CP_ASYNC16(sb + OFF_BH + dst_off, pbh + k);
        CP_ASYNC16(sb + OFF_BL + dst_off, pbl + k);
        CP_COMMIT();
    }

    const uint32_t aoff = (uint32_t)((lane & 15) * 48 + (lane >> 4) * 16 + wm * 32 * 48);
    const uint32_t boff = (uint32_t)((((lane >> 4) * 8) + (lane & 7)) * 48 +
                                     ((lane >> 3) & 1) * 16 + wn * 64 * 48);

    for (int c = 0; c < nch; ++c) {
        CP_WAIT(GSTAGES - 2);
        __syncthreads();
        if (c + GSTAGES - 1 < nch) {
            int s = c + GSTAGES - 1;
            uint32_t sb = smem + (uint32_t)(s % GSTAGES) * STAGE_BYTES;
            int k = s << 4;
            CP_ASYNC16(sb + OFF_AH + dst_off, pah + k);
            CP_ASYNC16(sb + OFF_AL + dst_off, pal + k);
            CP_ASYNC16(sb + OFF_BH + dst_off, pbh + k);
            CP_ASYNC16(sb + OFF_BL + dst_off, pbl + k);
            CP_COMMIT();
        }
        uint32_t sb = smem + (uint32_t)(c % GSTAGES) * STAGE_BYTES;

        uint32_t ah0[4], ah1[4], al0[4], al1[4], bhf[4][4], blf[4][4];
        ldsm4(ah0, sb + OFF_AH + aoff);
        ldsm4(ah1, sb + OFF_AH + aoff + 16 * 48);
        ldsm4(al0, sb + OFF_AL + aoff);
        ldsm4(al1, sb + OFF_AL + aoff + 16 * 48);
        #pragma unroll
        for (int j = 0; j < 4; ++j) {
            ldsm4(bhf[j], sb + OFF_BH + boff + (uint32_t)(j * 16 * 48));
            ldsm4(blf[j], sb + OFF_BL + boff + (uint32_t)(j * 16 * 48));
        }
        #pragma unroll
        for (int i = 0; i < 2; ++i) {
            const uint32_t* Ah = i ? ah1 : ah0;
            const uint32_t* Al = i ? al1 : al0;
            #pragma unroll
            for (int j = 0; j < 8; ++j) {
                uint32_t bh2[2] = { bhf[j >> 1][(j & 1) * 2], bhf[j >> 1][(j & 1) * 2 + 1] };
                uint32_t bl2[2] = { blf[j >> 1][(j & 1) * 2], blf[j >> 1][(j & 1) * 2 + 1] };
                mma16816(acc[i][j], Ah, bh2);
                mma16816(acc[i][j], Ah, bl2);
                mma16816(acc[i][j], Al, bh2);
            }
        }
    }

    // ---- epilogue: stage through smem, then coalesced output
    CP_WAIT(0);
    __syncthreads();
    float* stage = reinterpret_cast<float*>(dsm);   // [128][132] f32 = 67584B
    #pragma unroll
    for (int i = 0; i < 2; ++i)
        #pragma unroll
        for (int j = 0; j < 8; ++j) {
            int r = wm * 32 + i * 16 + (lane >> 2);
            int cc = wn * 64 + j * 8 + (lane & 3) * 2;
            stage[r * 132 + cc]           = acc[i][j][0];
            stage[r * 132 + cc + 1]       = acc[i][j][1];
            stage[(r + 8) * 132 + cc]     = acc[i][j][2];
            stage[(r + 8) * 132 + cc + 1] = acc[i][j][3];
        }
    __syncthreads();
    float* Cout = PARTIAL ? (C + (size_t)blockIdx.z * M * N) : C;
    for (int it = 0; it < 64; ++it) {
        int idx = it * 256 + tid;
        int r = idx >> 7, cc = idx & 127;
        int gn = n0 + cc;
        if (gn < N) {
            float v = stage[r * 132 + cc];
            if (BIAS) v += bias[gn];
            if (RES)  v += res[(size_t)(m0 + r) * N + gn];
            if (GELU) v = 0.5f * v * (1.0f + erff(v * 0.70710678118654752f));
            if (SPLIT) {
                __nv_bfloat16 hh, ll;
                split1(v, hh, ll);
                outh[(size_t)(m0 + r) * N + gn] = hh;
                outl[(size_t)(m0 + r) * N + gn] = ll;
            } else {
                Cout[(size_t)(m0 + r) * N + gn] = v;
            }
        }
    }
}

// ---------------- flash attention (64-q tile per block) -----------------------
#define AT_STRIDE 76
#define ATTN_SMEM (4 * 64 * AT_STRIDE * 4)   // 77824 bytes

__global__ __launch_bounds__(256)
void attn_flash_kernel(__nv_bfloat16* __restrict__ oh, __nv_bfloat16* __restrict__ ol) {
    extern __shared__ float sm[];
    float* Qs = sm;
    float* Ks = Qs + 64 * AT_STRIDE;
    float* Vs = Ks + 64 * AT_STRIDE;
    float* Ps = Vs + 64 * AT_STRIDE;

    const int qt = blockIdx.x;
    const int bh = blockIdx.y;
    const int b = bh / NH, h = bh % NH;
    const int tid = threadIdx.x;
    const int qg = tid >> 4;
    const int kg = tid & 15;
    const int q0 = qt * 64;
    const size_t base = (size_t)b * TSEQ * QKVN;

    #pragma unroll
    for (int i = 0; i < 4; ++i) {
        int f = tid + i * 256;
        int row = f >> 4, c4 = f & 15;
        *reinterpret_cast<float4*>(&Qs[row * AT_STRIDE + c4 * 4]) =
            *reinterpret_cast<const float4*>(&g_qkv[base + (size_t)(q0 + row) * QKVN + h * HS + c4 * 4]);
    }

    float acc[4][4];
    #pragma unroll
    for (int i = 0; i < 4; ++i)
        #pragma unroll
        for (int j = 0; j < 4; ++j) acc[i][j] = 0.f;
    float row_m[4] = {-1e30f, -1e30f, -1e30f, -1e30f};
    float row_l[4] = {0.f, 0.f, 0.f, 0.f};

    for (int t = 0; t <= qt; ++t) {
        __syncthreads();
        #pragma unroll
        for (int i = 0; i < 4; ++i) {
            int f = tid + i * 256;
            int row = f >> 4, c4 = f & 15;
            size_t g = base + (size_t)(t * 64 + row) * QKVN + h * HS + c4 * 4;
            *reinterpret_cast<float4*>(&Ks[row * AT_STRIDE + c4 * 4]) =
                *reinterpret_cast<const float4*>(&g_qkv[g + D]);
            *reinterpret_cast<float4*>(&Vs[row * AT_STRIDE + c4 * 4]) =
                *reinterpret_cast<const float4*>(&g_qkv[g + 2 * D]);
        }
        __syncthreads();

        float dp[4][4];
        #pragma unroll
        for (int i = 0; i < 4; ++i)
            #pragma unroll
            for (int j = 0; j < 4; ++j) dp[i][j] = 0.f;
        #pragma unroll
        for (int e4 = 0; e4 < 16; ++e4) {
            float4 qv[4], kv[4];
            #pragma unroll
            for (int i = 0; i < 4; ++i)
                qv[i] = *reinterpret_cast<const float4*>(&Qs[(qg * 4 + i) * AT_STRIDE + e4 * 4]);
            #pragma unroll
            for (int j = 0; j < 4; ++j)
                kv[j] = *reinterpret_cast<const float4*>(&Ks[(kg * 4 + j) * AT_STRIDE + e4 * 4]);
            #pragma unroll
            for (int i = 0; i < 4; ++i)
                #pragma unroll
                for (int j = 0; j < 4; ++j)
                    dp[i][j] = fmaf(qv[i].x, kv[j].x, fmaf(qv[i].y, kv[j].y,
                               fmaf(qv[i].z, kv[j].z, fmaf(qv[i].w, kv[j].w, dp[i][j]))));
        }

        const bool diag = (t == qt);
        float p[4][4];
        #pragma unroll
        for (int i = 0; i < 4; ++i) {
            int rglob = qg * 4 + i;
            float tm = -1e30f;
            #pragma unroll
            for (int j = 0; j < 4; ++j) {
                bool valid = !diag || (kg * 4 + j <= rglob);
                float sv = valid ? dp[i][j] : -1e30f;
                dp[i][j] = sv;
                tm = fmaxf(tm, sv);
            }
            #pragma unroll
            for (int o = 1; o < 16; o <<= 1)
                tm = fmaxf(tm, __shfl_xor_sync(0xffffffffu, tm, o));
            float newm = fmaxf(row_m[i], tm);
            float corr = fexp(row_m[i] - newm);
            row_m[i] = newm;
            float ts = 0.f;
            #pragma unroll
            for (int j = 0; j < 4; ++j) {
                float pv = (dp[i][j] > -1e29f) ? fexp(dp[i][j] - newm) : 0.f;
                p[i][j] = pv;
                ts += pv;
            }
            #pragma unroll
            for (int o = 1; o < 16; o <<= 1)
                ts += __shfl_xor_sync(0xffffffffu, ts, o);
            row_l[i] = row_l[i] * corr + ts;
            #pragma unroll
            for (int j = 0; j < 4; ++j) acc[i][j] *= corr;
        }

        #pragma unroll
        for (int i = 0; i < 4; ++i)
            #pragma unroll
            for (int j = 0; j < 4; ++j)
                Ps[(kg * 4 + j) * AT_STRIDE + qg * 4 + i] = p[i][j];
        __syncthreads();

        for (int k = 0; k < 64; ++k) {
            float4 pv = *reinterpret_cast<const float4*>(&Ps[k * AT_STRIDE + qg * 4]);
            float4 vv = *reinterpret_cast<const float4*>(&Vs[k * AT_STRIDE + kg * 4]);
            float pr[4] = {pv.x, pv.y, pv.z, pv.w};
            float vr[4] = {vv.x, vv.y, vv.z, vv.w};
            #pragma unroll
            for (int i = 0; i < 4; ++i)
                #pragma unroll
                for (int j = 0; j < 4; ++j)
                    acc[i][j] = fmaf(pr[i], vr[j], acc[i][j]);
        }
    }

    #pragma unroll
    for (int i = 0; i < 4; ++i) {
        float sc = 0.125f / row_l[i];
        size_t orow = ((size_t)(b * TSEQ + q0 + qg * 4 + i)) * D + h * HS + kg * 4;
        #pragma unroll
        for (int j = 0; j < 4; ++j) {
            __nv_bfloat16 hh, ll;
            split1(acc[i][j] * sc, hh, ll);
            oh[orow + j] = hh;
            ol[orow + j] = ll;
        }
    }
}

// ---------------- loss ---------------------------------------------------------
__global__ __launch_bounds__(512)
void loss_row_kernel(const float* __restrict__ logits,
                     const int* __restrict__ targets) {
    int row = blockIdx.x;
    const float* lr = logits + (size_t)row * VOCAB;
    int tid = threadIdx.x, lane = tid & 31, w = tid >> 5;
    __shared__ float r[16];

    float sum = 0.f;
    for (int n = tid; n < VOCAB; n += 512) sum += fexp(lr[n]);
    sum = warp_sum(sum);
    if (lane == 0) r[w] = sum;
    __syncthreads();
    if (tid == 0) {
        float t = 0.f;
        #pragma unroll
        for (int i = 0; i < 16; i++) t += r[i];
        g_contrib[row] = logf(t) - lr[targets[row]];
    }
}

__global__ void loss_final_kernel(float* __restrict__ d_out, int out_size) {
    int tid = threadIdx.x, lane = tid & 31, w = tid >> 5;
    float s = 0.f;
    for (int i = tid; i < ROWS; i += blockDim.x) s += g_contrib[i];
    __shared__ float r[8];
    s = warp_sum(s);
    if (lane == 0) r[w] = s;
    __syncthreads();
    if (tid == 0) {
        float t = 0.f;
        #pragma unroll
        for (int i = 0; i < 8; i++) t += r[i];
        float loss = t / (float)ROWS;
        size_t btv = (size_t)ROWS * VOCAB;
        if ((size_t)out_size > btv) d_out[btv] = loss;
    }
}

// ---------------- driver -------------------------------------------------------
template<bool BIAS, bool RES, bool GELU, bool SPLIT>
static void tc_gemm(const __nv_bfloat16* ah, const __nv_bfloat16* al,
                    const __nv_bfloat16* bh, const __nv_bfloat16* bl,
                    const float* bias, const float* res, float* C,
                    __nv_bfloat16* outh, __nv_bfloat16* outl,
                    int M, int N, int K) {
    cudaFuncSetAttribute(mma_gemm_kernel<BIAS, RES, GELU, SPLIT, false>,
                         cudaFuncAttributeMaxDynamicSharedMemorySize, GEMM_SMEM);
    dim3 grid(M / 128, (N + 127) / 128);
    mma_gemm_kernel<BIAS, RES, GELU, SPLIT, false><<<grid, 256, GEMM_SMEM>>>(
        ah, al, bh, bl, bias, res, C, outh, outl, M, N, K, 0);
}

// K-split GEMM into g_part, then reduce with bias + residual into outp (N must be D)
static void tc_gemm_ksplit(const __nv_bfloat16* ah, const __nv_bfloat16* al,
                           const __nv_bfloat16* bh, const __nv_bfloat16* bl,
                           const float* bias, float* outp, float* part,
                           int M, int N, int K, int S) {
    cudaFuncSetAttribute(mma_gemm_kernel<false, false, false, false, true>,
                         cudaFuncAttributeMaxDynamicSharedMemorySize, GEMM_SMEM);
    dim3 grid(M / 128, (N + 127) / 128, S);
    mma_gemm_kernel<false, false, false, false, true><<<grid, 256, GEMM_SMEM>>>(
        ah, al, bh, bl, nullptr, nullptr, part, nullptr, nullptr, M, N, K, K / S);
    ksplit_reduce_kernel<<<(M * N / 4 + 255) / 256, 256>>>(bias, outp, S);
}

extern "C" void kernel_launch(void* const* d_in, const int* in_sizes, int n_in,
                              void* d_out, int out_size) {
    const int*   idx     = (const int*)  d_in[0];
    const int*   targets = (const int*)  d_in[1];
    const float* wte     = (const float*)d_in[2];
    const float* wpe     = (const float*)d_in[3];
    const float* ln1_s   = (const float*)d_in[4];
    const float* ln1_b   = (const float*)d_in[5];
    const float* ln2_s   = (const float*)d_in[6];
    const float* ln2_b   = (const float*)d_in[7];
    const float* Wq      = (const float*)d_in[8];
    const float* bq      = (const float*)d_in[9];
    const float* Wk      = (const float*)d_in[10];
    const float* bk      = (const float*)d_in[11];
    const float* Wv      = (const float*)d_in[12];
    const float* bv      = (const float*)d_in[13];
    const float* Wo      = (const float*)d_in[14];
    const float* bo      = (const float*)d_in[15];
    const float* W1      = (const float*)d_in[16];
    const float* b1      = (const float*)d_in[17];
    const float* W2      = (const float*)d_in[18];
    const float* b2      = (const float*)d_in[19];
    const float* lnf_s   = (const float*)d_in[20];
    const float* lnf_b   = (const float*)d_in[21];

    float* out = (float*)d_out;

    float *gx, *gqkv, *gbc, *gpart;
    __nv_bfloat16 *ah, *al, *ah2, *al2, *wteh, *wtel, *qkvwh, *qkvwl, *woh, *wol, *w1h, *w1l, *w2h, *w2l;
    cudaGetSymbolAddress((void**)&gx,   g_x);
    cudaGetSymbolAddress((void**)&gqkv, g_qkv);
    cudaGetSymbolAddress((void**)&gbc,  g_bc2);
    cudaGetSymbolAddress((void**)&gpart, g_part);
    cudaGetSymbolAddress((void**)&ah,   g_ah);
    cudaGetSymbolAddress((void**)&al,   g_al);
    cudaGetSymbolAddress((void**)&ah2,  g_ah2);
    cudaGetSymbolAddress((void**)&al2,  g_al2);
    cudaGetSymbolAddress((void**)&wteh, g_wteh);
    cudaGetSymbolAddress((void**)&wtel, g_wtel);
    cudaGetSymbolAddress((void**)&qkvwh, g_qkvwh);
    cudaGetSymbolAddress((void**)&qkvwl, g_qkvwl);
    cudaGetSymbolAddress((void**)&woh,  g_woh);
    cudaGetSymbolAddress((void**)&wol,  g_wol);
    cudaGetSymbolAddress((void**)&w1h,  g_w1h);
    cudaGetSymbolAddress((void**)&w1l,  g_w1l);
    cudaGetSymbolAddress((void**)&w2h,  g_w2h);
    cudaGetSymbolAddress((void**)&w2l,  g_w2l);

    cudaFuncSetAttribute(attn_flash_kernel,
                         cudaFuncAttributeMaxDynamicSharedMemorySize, ATTN_SMEM);

    // ---- launch order: the profiler's captured slot was launch #4 last round,
    //      so place the first QKV GEMM at #4.
    // [1] embed
    embed_kernel<<<ROWS, 256>>>(idx, wte, wpe);
    // [2] qkv weight pack (both layers)
    {
        dim3 b(256), g((QKVN * D + 255) / 256, LAYERS);
        qkv_pack_kernel<<<g, b>>>(Wq, Wk, Wv, bq, bk, bv);
    }
    // [3] ln1 + split (layer 0)
    ln_split_kernel<<<ROWS, 256>>>(gx, ln1_s, ln1_b, ah, al);
    // [4] QKV GEMM layer 0  <-- ncu capture target
    tc_gemm<true, false, false, false>(ah, al, qkvwh, qkvwl,
        gbc, nullptr, gqkv, nullptr, nullptr, ROWS, QKVN, D);

    // remaining weight prep (before first use)
    {
        dim3 blk(32, 8);
        tsplit_kernel<<<dim3(D / 32, D / 32), blk>>>(Wo, woh, wol, D, D);
        tsplit_kernel<<<dim3(FF / 32, D / 32), blk>>>(W1, w1h, w1l, D, FF);
        tsplit_kernel<<<dim3(D / 32, FF / 32), blk>>>(W2, w2h, w2l, FF, D);
        tsplit_kernel<<<dim3(D / 32, D / 32), blk>>>(Wo + (size_t)D * D,
            woh + (size_t)D * D, wol + (size_t)D * D, D, D);
        tsplit_kernel<<<dim3(FF / 32, D / 32), blk>>>(W1 + (size_t)D * FF,
            w1h + (size_t)FF * D, w1l + (size_t)FF * D, D, FF);
        tsplit_kernel<<<dim3(D / 32, FF / 32), blk>>>(W2 + (size_t)FF * D,
            w2h + (size_t)D * FF, w2l + (size_t)D * FF, FF, D);
    }
    split4_kernel<<<(VOCAB * D / 4 + 255) / 256, 256>>>(wte, wteh, wtel, VOCAB * D / 4);

    for (int l = 0; l < LAYERS; l++) {
        if (l > 0) {
            ln_split_kernel<<<ROWS, 256>>>(gx, ln1_s + (size_t)l * D, ln1_b + (size_t)l * D, ah, al);
            tc_gemm<true, false, false, false>(ah, al,
                qkvwh + (size_t)l * QKVN * D, qkvwl + (size_t)l * QKVN * D,
                gbc + l * QKVN, nullptr, gqkv, nullptr, nullptr, ROWS, QKVN, D);
        }

        attn_flash_kernel<<<dim3(TSEQ / 64, BATCH * NH), 256, ATTN_SMEM>>>(ah, al);

        // x = x + att @ Wo^T + bo   (K-split x2: 192 CTAs instead of 96)
        tc_gemm_ksplit(ah, al,
            woh + (size_t)l * D * D, wol + (size_t)l * D * D,
            bo + (size_t)l * D, gx, gpart, ROWS, D, D, 2);

        ln_split_kernel<<<ROWS, 256>>>(gx, ln2_s + (size_t)l * D, ln2_b + (size_t)l * D, ah, al);
        tc_gemm<true, false, true, true>(ah, al,
            w1h + (size_t)l * FF * D, w1l + (size_t)l * FF * D,
            b1 + (size_t)l * FF, nullptr, nullptr, ah2, al2, ROWS, FF, D);

        // x = x + mid @ W2^T + b2   (K-split x4: 384 CTAs instead of 96)
        tc_gemm_ksplit(ah2, al2,
            w2h + (size_t)l * D * FF, w2l + (size_t)l * D * FF,
            b2 + (size_t)l * D, gx, gpart, ROWS, D, FF, 4);
    }

    ln_split_kernel<<<ROWS, 256>>>(gx, lnf_s, lnf_b, ah, al);
    // logits = h @ wte^T
    tc_gemm<false, false, false, false>(ah, al, wteh, wtel,
        nullptr, nullptr, out, nullptr, nullptr, ROWS, VOCAB, D);

    loss_row_kernel<<<ROWS, 512>>>(out, targets);
    loss_final_kernel<<<1, 256>>>(out, out_size);
}